// round 1
// baseline (speedup 1.0000x reference)
#include <cuda_runtime.h>
#include <cuda_bf16.h>
#include <math.h>

#define N_A 50000
#define N_B 50000
#define NT  100000
#define NE  800000
#define EHN 1600000
#define CC  128

// ---------------- device scratch (static, no allocation) ----------------
__device__ float g_agg [NT * 8];
__device__ float g_pe  [NT * 64];
__device__ float g_linA[N_A * CC];
__device__ float g_linB[N_B * CC];
__device__ float g_mA  [N_A * CC];
__device__ float g_mB  [N_B * CC];
__device__ float g_curA[N_A * CC];
__device__ float g_curB[N_B * CC];
__device__ float g_invA[N_A];
__device__ float g_invB[N_B];
__device__ int   g_cntA[N_A];
__device__ int   g_cntB[N_B];

// ---------------- helpers ----------------
__device__ __forceinline__ void red4(float* addr, float4 v) {
    asm volatile("red.global.add.v4.f32 [%0], {%1,%2,%3,%4};"
                 :: "l"(addr), "f"(v.x), "f"(v.y), "f"(v.z), "f"(v.w) : "memory");
}

// ---------------- degree count + inverse ----------------
__global__ void count_kernel(const int* __restrict__ dst, int* __restrict__ cnt, int E) {
    int e = blockIdx.x * blockDim.x + threadIdx.x;
    if (e < E) atomicAdd(&cnt[dst[e]], 1);
}

__global__ void inv_kernel(const int* __restrict__ cnt, float* __restrict__ inv, int N) {
    int i = blockIdx.x * blockDim.x + threadIdx.x;
    if (i < N) inv[i] = 1.0f / (float)max(cnt[i], 1);
}

// ---------------- homogeneous PE aggregation (once): agg += PE[hsrc] at hdst ----------------
__global__ void agg_scatter(const float* __restrict__ PE, const int* __restrict__ hsrc,
                            const int* __restrict__ hdst, float* __restrict__ agg, int E) {
    int e = blockIdx.x * blockDim.x + threadIdx.x;
    if (e >= E) return;
    int s = hsrc[e], d = hdst[e];
    float4 v0 = *(const float4*)(PE + (size_t)s * 8);
    float4 v1 = *(const float4*)(PE + (size_t)s * 8 + 4);
    red4(agg + (size_t)d * 8,     v0);
    red4(agg + (size_t)d * 8 + 4, v1);
}

// ---------------- phi MLP: pe = relu(agg@W1+b1)@W2+b2   [NT,8]->[NT,64] ----------------
__global__ void phi_kernel(const float* __restrict__ agg,
                           const float* __restrict__ W1, const float* __restrict__ b1,
                           const float* __restrict__ W2, const float* __restrict__ b2,
                           float* __restrict__ pe, int NTn) {
    __shared__ float sW1[8 * 64];
    __shared__ float sW2[64 * 64];
    __shared__ float sb1[64], sb2[64];
    __shared__ float hid[4][64];
    int tid = threadIdx.x;
    for (int i = tid; i < 512;  i += 256) sW1[i] = W1[i];
    for (int i = tid; i < 4096; i += 256) sW2[i] = W2[i];
    if (tid < 64) { sb1[tid] = b1[tid]; sb2[tid] = b2[tid]; }
    __syncthreads();
    int r = tid >> 6;      // 0..3  (row within block)
    int j = tid & 63;      // output column
    int row = blockIdx.x * 4 + r;
    if (row < NTn) {
        float a[8];
        #pragma unroll
        for (int k = 0; k < 8; k++) a[k] = agg[(size_t)row * 8 + k];
        float h = sb1[j];
        #pragma unroll
        for (int k = 0; k < 8; k++) h += a[k] * sW1[k * 64 + j];
        hid[r][j] = fmaxf(h, 0.0f);
    }
    __syncthreads();
    if (row < NTn) {
        float o = sb2[j];
        #pragma unroll
        for (int k = 0; k < 64; k++) o += hid[r][k] * sW2[k * 64 + j];
        pe[(size_t)row * 64 + j] = o;
    }
}

// ---------------- edge scatter: accum[dst] += x[src]   (128 ch, float4 per thread) ----------------
__global__ void scatter_kernel(const float* __restrict__ x, const int* __restrict__ src,
                               const int* __restrict__ dst, float* __restrict__ accum, int E) {
    int idx = blockIdx.x * blockDim.x + threadIdx.x;      // E*32 threads
    if (idx >= E * 32) return;
    int e = idx >> 5;
    int c = (idx & 31) * 4;
    int s = src[e], d = dst[e];
    float4 v = *(const float4*)(x + (size_t)s * CC + c);
    red4(accum + (size_t)d * CC + c, v);
}

// ---------------- fused GEMM:  out = [X0*rowScale? | X1] @ [W0;W1] + bias  (+LN+ReLU) ----------------
// N fixed = 128 output cols (one block owns full rows -> LN in-block).
#define BM 64
#define BK 16

template<bool DO_LN>
__global__ void __launch_bounds__(256)
gemm128(const float* __restrict__ X0, int K0,
        const float* __restrict__ X1, int K1,
        const float* __restrict__ rowScale,
        const float* __restrict__ W0, const float* __restrict__ W1,
        const float* __restrict__ bias,
        const float* __restrict__ gamma, const float* __restrict__ beta,
        float* __restrict__ out, int M)
{
    __shared__ float smem[BM * 128];       // 32KB, reused: As(1040) Bs(2048) then C-tile(8192)
    float* As = smem;                      // [BK][BM] padded stride 65
    float* Bs = smem + 1088;               // [BK][128]

    int tid = threadIdx.x;
    int m0  = blockIdx.x * BM;

    int tx = tid & 31;                     // n-group: cols tx*4..tx*4+3
    int ty = tid >> 5;                     // m-group: rows ty*8..ty*8+7
    float acc[8][4] = {};

    // A-load map: one float4 along k per thread
    int am  = tid >> 2;                    // 0..63
    int ak4 = (tid & 3) * 4;               // 0,4,8,12
    int gm  = m0 + am;
    // B-load map: two float4 per thread
    int bk = tid >> 5;                     // 0..7 (+8)
    int bn = (tid & 31) * 4;

    int K = K0 + K1;
    for (int k0 = 0; k0 < K; k0 += BK) {
        bool first = (k0 < K0);            // K0 % BK == 0 -> tile never straddles
        const float* Xp = first ? X0 : X1;
        int ld  = first ? K0 : K1;
        int kl  = first ? k0 : (k0 - K0);
        float4 av = make_float4(0.f, 0.f, 0.f, 0.f);
        if (gm < M) {
            av = *(const float4*)(Xp + (size_t)gm * ld + kl + ak4);
            if (rowScale != nullptr && first) {
                float s = rowScale[gm];
                av.x *= s; av.y *= s; av.z *= s; av.w *= s;
            }
        }
        const float* Wp = first ? W0 : W1;
        int wk = first ? k0 : (k0 - K0);
        float4 b0 = *(const float4*)(Wp + (size_t)(wk + bk)     * 128 + bn);
        float4 b1v = *(const float4*)(Wp + (size_t)(wk + bk + 8) * 128 + bn);

        __syncthreads();
        As[(ak4 + 0) * 65 + am] = av.x;
        As[(ak4 + 1) * 65 + am] = av.y;
        As[(ak4 + 2) * 65 + am] = av.z;
        As[(ak4 + 3) * 65 + am] = av.w;
        *(float4*)(Bs + bk * 128 + bn)       = b0;
        *(float4*)(Bs + (bk + 8) * 128 + bn) = b1v;
        __syncthreads();

        #pragma unroll
        for (int k = 0; k < BK; k++) {
            float a[8];
            #pragma unroll
            for (int i = 0; i < 8; i++) a[i] = As[k * 65 + ty * 8 + i];
            float4 b = *(const float4*)(Bs + k * 128 + tx * 4);
            #pragma unroll
            for (int i = 0; i < 8; i++) {
                acc[i][0] += a[i] * b.x;
                acc[i][1] += a[i] * b.y;
                acc[i][2] += a[i] * b.z;
                acc[i][3] += a[i] * b.w;
            }
        }
    }

    float4 bv = *(const float4*)(bias + tx * 4);

    if (!DO_LN) {
        #pragma unroll
        for (int i = 0; i < 8; i++) {
            int row = m0 + ty * 8 + i;
            if (row < M) {
                float4 o = make_float4(acc[i][0] + bv.x, acc[i][1] + bv.y,
                                       acc[i][2] + bv.z, acc[i][3] + bv.w);
                *(float4*)(out + (size_t)row * 128 + tx * 4) = o;
            }
        }
    } else {
        __syncthreads();                   // done reading As/Bs
        #pragma unroll
        for (int i = 0; i < 8; i++) {
            float4 o = make_float4(acc[i][0] + bv.x, acc[i][1] + bv.y,
                                   acc[i][2] + bv.z, acc[i][3] + bv.w);
            *(float4*)(smem + (ty * 8 + i) * 128 + tx * 4) = o;
        }
        __syncthreads();
        int warp = tid >> 5, lane = tid & 31;
        float4 g = *(const float4*)(gamma + lane * 4);
        float4 be = *(const float4*)(beta + lane * 4);
        for (int r = warp; r < BM; r += 8) {
            float4 v = *(const float4*)(smem + r * 128 + lane * 4);
            float s  = v.x + v.y + v.z + v.w;
            float ss = v.x * v.x + v.y * v.y + v.z * v.z + v.w * v.w;
            #pragma unroll
            for (int off = 16; off; off >>= 1) {
                s  += __shfl_xor_sync(0xffffffffu, s,  off);
                ss += __shfl_xor_sync(0xffffffffu, ss, off);
            }
            float mu   = s * (1.0f / 128.0f);
            float var  = ss * (1.0f / 128.0f) - mu * mu;
            float rstd = rsqrtf(var + 1e-5f);
            int row = m0 + r;
            if (row < M) {
                float4 o;
                o.x = fmaxf((v.x - mu) * rstd * g.x + be.x, 0.0f);
                o.y = fmaxf((v.y - mu) * rstd * g.y + be.y, 0.0f);
                o.z = fmaxf((v.z - mu) * rstd * g.z + be.z, 0.0f);
                o.w = fmaxf((v.w - mu) * rstd * g.w + be.w, 0.0f);
                *(float4*)(out + (size_t)row * 128 + lane * 4) = o;
            }
        }
    }
}

// ---------------- launch ----------------
extern "C" void kernel_launch(void* const* d_in, const int* in_sizes, int n_in,
                              void* d_out, int out_size)
{
    const float* xA     = (const float*)d_in[0];
    const float* xB     = (const float*)d_in[1];
    const float* PE     = (const float*)d_in[2];
    const int*   edgeAB = (const int*)  d_in[3];
    const int*   edgeBA = (const int*)  d_in[4];
    const int*   hedge  = (const int*)  d_in[5];
    const float* sWl    = (const float*)d_in[6];
    const float* sbl    = (const float*)d_in[7];
    const float* sWr    = (const float*)d_in[8];
    const float* lng    = (const float*)d_in[9];
    const float* lnb    = (const float*)d_in[10];
    const float* pW1    = (const float*)d_in[11];
    const float* pb1    = (const float*)d_in[12];
    const float* pW2    = (const float*)d_in[13];
    const float* pb2    = (const float*)d_in[14];
    const float* peW    = (const float*)d_in[15];
    const float* peb    = (const float*)d_in[16];
    float* out = (float*)d_out;

    float *agg, *pe, *linA, *linB, *mA, *mB, *curA, *curB, *invA, *invB;
    int *cntA, *cntB;
    cudaGetSymbolAddress((void**)&agg,  g_agg);
    cudaGetSymbolAddress((void**)&pe,   g_pe);
    cudaGetSymbolAddress((void**)&linA, g_linA);
    cudaGetSymbolAddress((void**)&linB, g_linB);
    cudaGetSymbolAddress((void**)&mA,   g_mA);
    cudaGetSymbolAddress((void**)&mB,   g_mB);
    cudaGetSymbolAddress((void**)&curA, g_curA);
    cudaGetSymbolAddress((void**)&curB, g_curB);
    cudaGetSymbolAddress((void**)&invA, g_invA);
    cudaGetSymbolAddress((void**)&invB, g_invB);
    cudaGetSymbolAddress((void**)&cntA, g_cntA);
    cudaGetSymbolAddress((void**)&cntB, g_cntB);

    // ---- degree counts (layer-invariant) ----
    cudaMemsetAsync(cntA, 0, N_A * sizeof(int));
    cudaMemsetAsync(cntB, 0, N_B * sizeof(int));
    count_kernel<<<(NE + 255) / 256, 256>>>(edgeAB + NE, cntB, NE);  // A->B dst
    count_kernel<<<(NE + 255) / 256, 256>>>(edgeBA + NE, cntA, NE);  // B->A dst
    inv_kernel<<<(N_A + 255) / 256, 256>>>(cntA, invA, N_A);
    inv_kernel<<<(N_B + 255) / 256, 256>>>(cntB, invB, N_B);

    // ---- homogeneous PE aggregation (layer-invariant: PE never updated) ----
    cudaMemcpyAsync(agg, PE, (size_t)NT * 8 * sizeof(float), cudaMemcpyDeviceToDevice);
    agg_scatter<<<(EHN + 255) / 256, 256>>>(PE, hedge, hedge + EHN, agg, EHN);

    const float* srcA = xA;
    const float* srcB = xB;
    dim3 gGrid((N_A + BM - 1) / BM);

    for (int l = 0; l < 2; l++) {
        // phi MLP -> pe [NT,64]
        phi_kernel<<<(NT + 3) / 4, 256>>>(agg, pW1 + l * 512, pb1 + l * 64,
                                          pW2 + l * 4096, pb2 + l * 64, pe, NT);

        // pe-linear: lin = [x | pe] @ pe_W[l] + pe_b[l]
        const float* W0 = peW + (size_t)l * 192 * 128;
        const float* W1 = W0 + 128 * 128;
        gemm128<false><<<gGrid, 256>>>(srcA, 128, pe, 64, nullptr,
                                       W0, W1, peb + l * 128,
                                       nullptr, nullptr, linA, N_A);
        gemm128<false><<<gGrid, 256>>>(srcB, 128, pe + (size_t)N_A * 64, 64, nullptr,
                                       W0, W1, peb + l * 128,
                                       nullptr, nullptr, linB, N_B);

        // edge means (sums; 1/cnt folded into next GEMM)
        cudaMemsetAsync(mA, 0, (size_t)N_A * CC * sizeof(float));
        cudaMemsetAsync(mB, 0, (size_t)N_B * CC * sizeof(float));
        scatter_kernel<<<(NE * 32) / 256, 256>>>(linA, edgeAB, edgeAB + NE, mB, NE);
        scatter_kernel<<<(NE * 32) / 256, 256>>>(linB, edgeBA, edgeBA + NE, mA, NE);

        float* outA = (l == 1) ? out                        : curA;
        float* outB = (l == 1) ? out + (size_t)N_A * CC     : curB;

        // SAGE + LN + ReLU. Weights: idx0 -> B, idx1 -> A. LN: idx0 -> A, idx1 -> B.
        gemm128<true><<<gGrid, 256>>>(mB, 128, linB, 128, invB,
                                      sWl + (size_t)(l * 2 + 0) * 16384,
                                      sWr + (size_t)(l * 2 + 0) * 16384,
                                      sbl + (l * 2 + 0) * 128,
                                      lng + (l * 2 + 1) * 128, lnb + (l * 2 + 1) * 128,
                                      outB, N_B);
        gemm128<true><<<gGrid, 256>>>(mA, 128, linA, 128, invA,
                                      sWl + (size_t)(l * 2 + 1) * 16384,
                                      sWr + (size_t)(l * 2 + 1) * 16384,
                                      sbl + (l * 2 + 1) * 128,
                                      lng + (l * 2 + 0) * 128, lnb + (l * 2 + 0) * 128,
                                      outA, N_A);

        srcA = curA;
        srcB = curB;
    }
}

// round 3
// speedup vs baseline: 1.3568x; 1.3568x over previous
#include <cuda_runtime.h>
#include <cuda_bf16.h>
#include <math.h>
#include <stdint.h>

#define N_A 50000
#define N_B 50000
#define NT  100000
#define NE  800000
#define EHN 1600000
#define CC  128

// ---------------- device scratch (static, no allocation) ----------------
__device__ float g_agg [NT * 8];
__device__ float g_pe  [NT * 64];
__device__ float g_linA[N_A * CC];
__device__ float g_linB[N_B * CC];
__device__ float g_mA  [N_A * CC];
__device__ float g_mB  [N_B * CC];
__device__ float g_curA[N_A * CC];
__device__ float g_curB[N_B * CC];
__device__ float g_invA[N_A];
__device__ float g_invB[N_B];
__device__ int   g_cntA[N_A];
__device__ int   g_cntB[N_B];
__device__ float g_WTpe  [2 * 128 * 192];   // transposed pe_W per layer: [n=128][k=192], tf32-rounded
__device__ float g_WTsage[4 * 128 * 256];   // transposed [Wl;Wr] per (layer,etype): [n=128][k=256]

// ---------------- helpers ----------------
__device__ __forceinline__ uint32_t smem_u32(const void* p) {
    uint32_t a;
    asm("{ .reg .u64 t; cvta.to.shared.u64 t, %1; cvt.u32.u64 %0, t; }" : "=r"(a) : "l"(p));
    return a;
}

__device__ __forceinline__ uint32_t cvt_tf32(float f) {
    uint32_t r;
    asm("cvt.rna.tf32.f32 %0, %1;" : "=r"(r) : "f"(f));
    return r;
}

__device__ __forceinline__ float tf32_round(float f) {
    uint32_t r = cvt_tf32(f);
    return __uint_as_float(r);
}

__device__ __forceinline__ void mma_tf32(float c[4], const uint32_t a[4],
                                         uint32_t b0, uint32_t b1) {
    asm volatile(
        "mma.sync.aligned.m16n8k8.row.col.f32.tf32.tf32.f32 "
        "{%0,%1,%2,%3}, {%4,%5,%6,%7}, {%8,%9}, {%0,%1,%2,%3};"
        : "+f"(c[0]), "+f"(c[1]), "+f"(c[2]), "+f"(c[3])
        : "r"(a[0]), "r"(a[1]), "r"(a[2]), "r"(a[3]), "r"(b0), "r"(b1));
}

__device__ __forceinline__ void cpasync16(uint32_t daddr, const float* g, bool pred) {
    int sz = pred ? 16 : 0;
    asm volatile("cp.async.cg.shared.global [%0], [%1], 16, %2;"
                 :: "r"(daddr), "l"(g), "r"(sz) : "memory");
}
#define CP_COMMIT() asm volatile("cp.async.commit_group;" ::: "memory")

__device__ __forceinline__ void red4(float* addr, float4 v) {
    asm volatile("red.global.add.v4.f32 [%0], {%1,%2,%3,%4};"
                 :: "l"(addr), "f"(v.x), "f"(v.y), "f"(v.z), "f"(v.w) : "memory");
}

// ---------------- small kernels ----------------
__global__ void count_kernel(const int* __restrict__ dst, int* __restrict__ cnt, int E) {
    int e = blockIdx.x * blockDim.x + threadIdx.x;
    if (e < E) atomicAdd(&cnt[dst[e]], 1);
}

__global__ void inv_kernel(const int* __restrict__ cnt, float* __restrict__ inv, int N) {
    int i = blockIdx.x * blockDim.x + threadIdx.x;
    if (i < N) inv[i] = 1.0f / (float)max(cnt[i], 1);
}

__global__ void agg_scatter(const float* __restrict__ PE, const int* __restrict__ hsrc,
                            const int* __restrict__ hdst, float* __restrict__ agg, int E) {
    int e = blockIdx.x * blockDim.x + threadIdx.x;
    if (e >= E) return;
    int s = hsrc[e], d = hdst[e];
    float4 v0 = *(const float4*)(PE + (size_t)s * 8);
    float4 v1 = *(const float4*)(PE + (size_t)s * 8 + 4);
    red4(agg + (size_t)d * 8,     v0);
    red4(agg + (size_t)d * 8 + 4, v1);
}

// WT[n][k] = tf32_round( k < Kl ? Wl[k][n] : Wr[k-Kl][n] )
__global__ void transpose_pack(const float* __restrict__ Wl, const float* __restrict__ Wr,
                               float* __restrict__ WT, int Kl, int Kr) {
    int K = Kl + Kr;
    int idx = blockIdx.x * blockDim.x + threadIdx.x;
    if (idx >= 128 * K) return;
    int n = idx / K, k = idx % K;
    float w = (k < Kl) ? Wl[(size_t)k * 128 + n] : Wr[(size_t)(k - Kl) * 128 + n];
    WT[idx] = tf32_round(w);
}

__global__ void phi_kernel(const float* __restrict__ agg,
                           const float* __restrict__ W1, const float* __restrict__ b1,
                           const float* __restrict__ W2, const float* __restrict__ b2,
                           float* __restrict__ pe, int NTn) {
    __shared__ float sW1[8 * 64];
    __shared__ float sW2[64 * 64];
    __shared__ float sb1[64], sb2[64];
    __shared__ float hid[4][64];
    int tid = threadIdx.x;
    for (int i = tid; i < 512;  i += 256) sW1[i] = W1[i];
    for (int i = tid; i < 4096; i += 256) sW2[i] = W2[i];
    if (tid < 64) { sb1[tid] = b1[tid]; sb2[tid] = b2[tid]; }
    __syncthreads();
    int r = tid >> 6;
    int j = tid & 63;
    int row = blockIdx.x * 4 + r;
    if (row < NTn) {
        float a[8];
        #pragma unroll
        for (int k = 0; k < 8; k++) a[k] = agg[(size_t)row * 8 + k];
        float h = sb1[j];
        #pragma unroll
        for (int k = 0; k < 8; k++) h += a[k] * sW1[k * 64 + j];
        hid[r][j] = fmaxf(h, 0.0f);
    }
    __syncthreads();
    if (row < NTn) {
        float o = sb2[j];
        #pragma unroll
        for (int k = 0; k < 64; k++) o += hid[r][k] * sW2[k * 64 + j];
        pe[(size_t)row * 64 + j] = o;
    }
}

// accum[dst] += x[src] * inv[dst]  (mean folded in here)
__global__ void scatter_kernel(const float* __restrict__ x, const int* __restrict__ src,
                               const int* __restrict__ dst, const float* __restrict__ inv,
                               float* __restrict__ accum, int E) {
    int idx = blockIdx.x * blockDim.x + threadIdx.x;
    if (idx >= E * 32) return;
    int e = idx >> 5;
    int c = (idx & 31) * 4;
    int s = src[e], d = dst[e];
    float sc = inv[d];
    float4 v = *(const float4*)(x + (size_t)s * CC + c);
    v.x *= sc; v.y *= sc; v.z *= sc; v.w *= sc;
    red4(accum + (size_t)d * CC + c, v);
}

// ---------------- tf32 mma.sync GEMM ----------------
// out[M,128] = [X0 | X1] @ WT^T + bias  (+LN+ReLU if DO_LN)
// Block: 256 thr (8 warps, 4x2). BM=128, BN=128, BK=16, double-buffered cp.async.
// smem floats: bias 128 | gamma 128 | beta 128 | sum 128 | ss 128 | As 2*2560 | Bs 2*2560
#define GEMM_SMEM_F (640 + 2 * 2560 + 2 * 2560)
#define TILE_F 2560          // 128 rows * 20 floats

__device__ __forceinline__ void load_tile(
    const float* __restrict__ X0, int K0, const float* __restrict__ X1, int K1,
    const float* __restrict__ WT, int K, int m0, int M, int t,
    uint32_t asAddr, uint32_t bsAddr, int tid)
{
    int kb = t * 16;
    #pragma unroll
    for (int i = 0; i < 2; i++) {
        int f = i * 256 + tid;
        int row = f >> 2, q = f & 3;
        int kk = kb + q * 4;
        bool pred = (m0 + row) < M;
        const float* src = (kk < K0)
            ? X0 + (size_t)(m0 + row) * K0 + kk
            : X1 + (size_t)(m0 + row) * K1 + (kk - K0);
        cpasync16(asAddr + (uint32_t)(row * 20 + q * 4) * 4, src, pred);
    }
    #pragma unroll
    for (int i = 0; i < 2; i++) {
        int f = i * 256 + tid;
        int n = f >> 2, q = f & 3;
        cpasync16(bsAddr + (uint32_t)(n * 20 + q * 4) * 4,
                  WT + (size_t)n * K + kb + q * 4, true);
    }
    CP_COMMIT();
}

template<bool DO_LN>
__global__ void __launch_bounds__(256, 2)
gemm_mma(const float* __restrict__ X0, int K0,
         const float* __restrict__ X1, int K1,
         const float* __restrict__ WT, int K,
         const float* __restrict__ bias,
         const float* __restrict__ gamma, const float* __restrict__ beta,
         float* __restrict__ out, int M)
{
    extern __shared__ float sm[];
    float* s_bias  = sm;
    float* s_gamma = sm + 128;
    float* s_beta  = sm + 256;
    float* s_sum   = sm + 384;
    float* s_ss    = sm + 512;
    float* As      = sm + 640;
    float* Bs      = As + 2 * TILE_F;

    int tid  = threadIdx.x;
    int lane = tid & 31;
    int warp = tid >> 5;
    int wm = warp & 3;        // 0..3 -> 32-row slab
    int wn = warp >> 2;       // 0..1 -> 64-col slab
    int m0 = blockIdx.x * 128;

    if (tid < 128) {
        s_bias[tid] = bias[tid];
        if (DO_LN) {
            s_gamma[tid] = gamma[tid];
            s_beta[tid]  = beta[tid];
            s_sum[tid] = 0.0f;
            s_ss[tid]  = 0.0f;
        }
    }

    uint32_t asAddr = smem_u32(As);
    uint32_t bsAddr = smem_u32(Bs);

    float c[2][8][4];
    #pragma unroll
    for (int mt = 0; mt < 2; mt++)
        #pragma unroll
        for (int nt = 0; nt < 8; nt++)
            #pragma unroll
            for (int j = 0; j < 4; j++) c[mt][nt][j] = 0.0f;

    const int T = K / 16;
    load_tile(X0, K0, X1, K1, WT, K, m0, M, 0, asAddr, bsAddr, tid);
    load_tile(X0, K0, X1, K1, WT, K, m0, M, 1, asAddr + TILE_F * 4, bsAddr + TILE_F * 4, tid);

    for (int t = 0; t < T; t++) {
        if (t + 1 < T) asm volatile("cp.async.wait_group 1;" ::: "memory");
        else           asm volatile("cp.async.wait_group 0;" ::: "memory");
        __syncthreads();

        const float* Ab = As + (t & 1) * TILE_F;
        const float* Bb = Bs + (t & 1) * TILE_F;
        #pragma unroll
        for (int ks = 0; ks < 2; ks++) {
            int k0 = ks * 8 + (lane & 3);
            uint32_t a[2][4];
            #pragma unroll
            for (int mt = 0; mt < 2; mt++) {
                int rb = wm * 32 + mt * 16 + (lane >> 2);
                a[mt][0] = cvt_tf32(Ab[rb * 20 + k0]);
                a[mt][1] = cvt_tf32(Ab[(rb + 8) * 20 + k0]);
                a[mt][2] = cvt_tf32(Ab[rb * 20 + k0 + 4]);
                a[mt][3] = cvt_tf32(Ab[(rb + 8) * 20 + k0 + 4]);
            }
            #pragma unroll
            for (int nt = 0; nt < 8; nt++) {
                int nb = wn * 64 + nt * 8 + (lane >> 2);
                uint32_t b0 = __float_as_uint(Bb[nb * 20 + k0]);      // pre-rounded tf32
                uint32_t b1 = __float_as_uint(Bb[nb * 20 + k0 + 4]);
                mma_tf32(c[0][nt], a[0], b0, b1);
                mma_tf32(c[1][nt], a[1], b0, b1);
            }
        }
        __syncthreads();
        if (t + 2 < T)
            load_tile(X0, K0, X1, K1, WT, K, m0, M, t + 2,
                      asAddr + (uint32_t)(t & 1) * TILE_F * 4,
                      bsAddr + (uint32_t)(t & 1) * TILE_F * 4, tid);
    }

    // ---- add bias ----
    #pragma unroll
    for (int nt = 0; nt < 8; nt++) {
        int col = wn * 64 + nt * 8 + 2 * (lane & 3);
        float bx = s_bias[col], by = s_bias[col + 1];
        #pragma unroll
        for (int mt = 0; mt < 2; mt++) {
            c[mt][nt][0] += bx; c[mt][nt][1] += by;
            c[mt][nt][2] += bx; c[mt][nt][3] += by;
        }
    }

    if (!DO_LN) {
        #pragma unroll
        for (int mt = 0; mt < 2; mt++)
            #pragma unroll
            for (int h = 0; h < 2; h++) {
                int row = m0 + wm * 32 + mt * 16 + (lane >> 2) + h * 8;
                if (row < M) {
                    #pragma unroll
                    for (int nt = 0; nt < 8; nt++) {
                        int col = wn * 64 + nt * 8 + 2 * (lane & 3);
                        float2 o = make_float2(c[mt][nt][h * 2], c[mt][nt][h * 2 + 1]);
                        *(float2*)(out + (size_t)row * 128 + col) = o;
                    }
                }
            }
        return;
    }

    // ---- LayerNorm + ReLU ----
    #pragma unroll
    for (int mt = 0; mt < 2; mt++)
        #pragma unroll
        for (int h = 0; h < 2; h++) {
            float s = 0.f, q = 0.f;
            #pragma unroll
            for (int nt = 0; nt < 8; nt++) {
                float v0 = c[mt][nt][h * 2], v1 = c[mt][nt][h * 2 + 1];
                s += v0 + v1;
                q += v0 * v0 + v1 * v1;
            }
            s += __shfl_xor_sync(0xffffffffu, s, 1);
            s += __shfl_xor_sync(0xffffffffu, s, 2);
            q += __shfl_xor_sync(0xffffffffu, q, 1);
            q += __shfl_xor_sync(0xffffffffu, q, 2);
            if ((lane & 3) == 0) {
                int rl = wm * 32 + mt * 16 + (lane >> 2) + h * 8;
                atomicAdd(&s_sum[rl], s);
                atomicAdd(&s_ss[rl], q);
            }
        }
    __syncthreads();
    #pragma unroll
    for (int mt = 0; mt < 2; mt++)
        #pragma unroll
        for (int h = 0; h < 2; h++) {
            int rl = wm * 32 + mt * 16 + (lane >> 2) + h * 8;
            int row = m0 + rl;
            float mu   = s_sum[rl] * (1.0f / 128.0f);
            float var  = s_ss[rl] * (1.0f / 128.0f) - mu * mu;
            float rstd = rsqrtf(var + 1e-5f);
            if (row < M) {
                #pragma unroll
                for (int nt = 0; nt < 8; nt++) {
                    int col = wn * 64 + nt * 8 + 2 * (lane & 3);
                    float2 o;
                    o.x = fmaxf((c[mt][nt][h * 2]     - mu) * rstd * s_gamma[col]     + s_beta[col],     0.f);
                    o.y = fmaxf((c[mt][nt][h * 2 + 1] - mu) * rstd * s_gamma[col + 1] + s_beta[col + 1], 0.f);
                    *(float2*)(out + (size_t)row * 128 + col) = o;
                }
            }
        }
}

// ---------------- launch ----------------
extern "C" void kernel_launch(void* const* d_in, const int* in_sizes, int n_in,
                              void* d_out, int out_size)
{
    const float* xA     = (const float*)d_in[0];
    const float* xB     = (const float*)d_in[1];
    const float* PE     = (const float*)d_in[2];
    const int*   edgeAB = (const int*)  d_in[3];
    const int*   edgeBA = (const int*)  d_in[4];
    const int*   hedge  = (const int*)  d_in[5];
    const float* sWl    = (const float*)d_in[6];
    const float* sbl    = (const float*)d_in[7];
    const float* sWr    = (const float*)d_in[8];
    const float* lng    = (const float*)d_in[9];
    const float* lnb    = (const float*)d_in[10];
    const float* pW1    = (const float*)d_in[11];
    const float* pb1    = (const float*)d_in[12];
    const float* pW2    = (const float*)d_in[13];
    const float* pb2    = (const float*)d_in[14];
    const float* peW    = (const float*)d_in[15];
    const float* peb    = (const float*)d_in[16];
    float* out = (float*)d_out;

    float *agg, *pe, *linA, *linB, *mA, *mB, *curA, *curB, *invA, *invB, *WTpe, *WTsage;
    int *cntA, *cntB;
    cudaGetSymbolAddress((void**)&agg,    g_agg);
    cudaGetSymbolAddress((void**)&pe,     g_pe);
    cudaGetSymbolAddress((void**)&linA,   g_linA);
    cudaGetSymbolAddress((void**)&linB,   g_linB);
    cudaGetSymbolAddress((void**)&mA,     g_mA);
    cudaGetSymbolAddress((void**)&mB,     g_mB);
    cudaGetSymbolAddress((void**)&curA,   g_curA);
    cudaGetSymbolAddress((void**)&curB,   g_curB);
    cudaGetSymbolAddress((void**)&invA,   g_invA);
    cudaGetSymbolAddress((void**)&invB,   g_invB);
    cudaGetSymbolAddress((void**)&cntA,   g_cntA);
    cudaGetSymbolAddress((void**)&cntB,   g_cntB);
    cudaGetSymbolAddress((void**)&WTpe,   g_WTpe);
    cudaGetSymbolAddress((void**)&WTsage, g_WTsage);

    // ---- degree counts + inverse (layer-invariant) ----
    cudaMemsetAsync(cntA, 0, N_A * sizeof(int));
    cudaMemsetAsync(cntB, 0, N_B * sizeof(int));
    count_kernel<<<(NE + 255) / 256, 256>>>(edgeAB + NE, cntB, NE);
    count_kernel<<<(NE + 255) / 256, 256>>>(edgeBA + NE, cntA, NE);
    inv_kernel<<<(N_A + 255) / 256, 256>>>(cntA, invA, N_A);
    inv_kernel<<<(N_B + 255) / 256, 256>>>(cntB, invB, N_B);

    // ---- homogeneous PE aggregation (layer-invariant) ----
    cudaMemcpyAsync(agg, PE, (size_t)NT * 8 * sizeof(float), cudaMemcpyDeviceToDevice);
    agg_scatter<<<(EHN + 255) / 256, 256>>>(PE, hedge, hedge + EHN, agg, EHN);

    // ---- transpose/pack (+ tf32-round) weights ----
    for (int l = 0; l < 2; l++) {
        transpose_pack<<<(128 * 192 + 255) / 256, 256>>>(
            peW + (size_t)l * 192 * 128, peW, WTpe + (size_t)l * 128 * 192, 192, 0);
        for (int e = 0; e < 2; e++) {
            int li = l * 2 + e;
            transpose_pack<<<(128 * 256 + 255) / 256, 256>>>(
                sWl + (size_t)li * 16384, sWr + (size_t)li * 16384,
                WTsage + (size_t)li * 128 * 256, 128, 128);
        }
    }

    const float* srcA = xA;
    const float* srcB = xB;
    dim3 gGrid((N_A + 127) / 128);
    size_t gsm = GEMM_SMEM_F * sizeof(float);

    for (int l = 0; l < 2; l++) {
        phi_kernel<<<(NT + 3) / 4, 256>>>(agg, pW1 + l * 512, pb1 + l * 64,
                                          pW2 + l * 4096, pb2 + l * 64, pe, NT);

        // pe-linear: lin = [x | pe] @ pe_W[l] + pe_b[l]   (K = 192)
        const float* wt = WTpe + (size_t)l * 128 * 192;
        gemm_mma<false><<<gGrid, 256, gsm>>>(srcA, 128, pe, 64,
                                             wt, 192, peb + l * 128,
                                             nullptr, nullptr, linA, N_A);
        gemm_mma<false><<<gGrid, 256, gsm>>>(srcB, 128, pe + (size_t)N_A * 64, 64,
                                             wt, 192, peb + l * 128,
                                             nullptr, nullptr, linB, N_B);

        // edge means (inv-degree folded into scatter)
        cudaMemsetAsync(mA, 0, (size_t)N_A * CC * sizeof(float));
        cudaMemsetAsync(mB, 0, (size_t)N_B * CC * sizeof(float));
        scatter_kernel<<<(NE * 32) / 256, 256>>>(linA, edgeAB, edgeAB + NE, invB, mB, NE);
        scatter_kernel<<<(NE * 32) / 256, 256>>>(linB, edgeBA, edgeBA + NE, invA, mA, NE);

        float* outA = (l == 1) ? out                    : curA;
        float* outB = (l == 1) ? out + (size_t)N_A * CC : curB;

        // SAGE + LN + ReLU (K = 256). Weight idx0 -> B-update, idx1 -> A-update.
        gemm_mma<true><<<gGrid, 256, gsm>>>(mB, 128, linB, 128,
                                            WTsage + (size_t)(l * 2 + 0) * 128 * 256, 256,
                                            sbl + (l * 2 + 0) * 128,
                                            lng + (l * 2 + 1) * 128, lnb + (l * 2 + 1) * 128,
                                            outB, N_B);
        gemm_mma<true><<<gGrid, 256, gsm>>>(mA, 128, linA, 128,
                                            WTsage + (size_t)(l * 2 + 1) * 128 * 256, 256,
                                            sbl + (l * 2 + 1) * 128,
                                            lng + (l * 2 + 0) * 128, lnb + (l * 2 + 0) * 128,
                                            outA, N_A);

        srcA = curA;
        srcB = curB;
    }
}

// round 4
// speedup vs baseline: 1.6914x; 1.2466x over previous
#include <cuda_runtime.h>
#include <cuda_bf16.h>
#include <math.h>
#include <stdint.h>

#define N_A 50000
#define N_B 50000
#define NT  100000
#define NE  800000
#define EHN 1600000
#define CC  128

// ---------------- device scratch (static, no allocation) ----------------
__device__ float g_agg [NT * 8];
__device__ float g_pe  [NT * 64];
__device__ float g_lin [NT * CC];     // A rows [0,N_A), B rows [N_A,NT)
__device__ float g_m   [NT * CC];     // means, same layout
__device__ float g_cur [NT * CC];     // layer output, same layout
__device__ float g_invA[N_A];
__device__ float g_invB[N_B];
__device__ int   g_cntA[N_A];
__device__ int   g_cntB[N_B];
__device__ int   g_offA[N_A + 1];
__device__ int   g_offB[N_B + 1];
__device__ int   g_csrAB[NE];         // src(A) ids grouped by dst(B)
__device__ int   g_csrBA[NE];         // src(B) ids grouped by dst(A)
__device__ float g_WTpe  [2 * 128 * 192];
__device__ float g_WTsage[4 * 128 * 256];

// ---------------- helpers ----------------
__device__ __forceinline__ uint32_t smem_u32(const void* p) {
    uint32_t a;
    asm("{ .reg .u64 t; cvta.to.shared.u64 t, %1; cvt.u32.u64 %0, t; }" : "=r"(a) : "l"(p));
    return a;
}

__device__ __forceinline__ uint32_t cvt_tf32(float f) {
    uint32_t r;
    asm("cvt.rna.tf32.f32 %0, %1;" : "=r"(r) : "f"(f));
    return r;
}

__device__ __forceinline__ void mma_tf32(float c[4], const uint32_t a[4],
                                         uint32_t b0, uint32_t b1) {
    asm volatile(
        "mma.sync.aligned.m16n8k8.row.col.f32.tf32.tf32.f32 "
        "{%0,%1,%2,%3}, {%4,%5,%6,%7}, {%8,%9}, {%0,%1,%2,%3};"
        : "+f"(c[0]), "+f"(c[1]), "+f"(c[2]), "+f"(c[3])
        : "r"(a[0]), "r"(a[1]), "r"(a[2]), "r"(a[3]), "r"(b0), "r"(b1));
}

__device__ __forceinline__ void cpasync16(uint32_t daddr, const float* g, bool pred) {
    int sz = pred ? 16 : 0;
    asm volatile("cp.async.cg.shared.global [%0], [%1], 16, %2;"
                 :: "r"(daddr), "l"(g), "r"(sz) : "memory");
}
#define CP_COMMIT() asm volatile("cp.async.commit_group;" ::: "memory")

__device__ __forceinline__ void red4(float* addr, float4 v) {
    asm volatile("red.global.add.v4.f32 [%0], {%1,%2,%3,%4};"
                 :: "l"(addr), "f"(v.x), "f"(v.y), "f"(v.z), "f"(v.w) : "memory");
}

// ---------------- graph preprocessing ----------------
__global__ void count_kernel(const int* __restrict__ dst, int* __restrict__ cnt, int E) {
    int e = blockIdx.x * blockDim.x + threadIdx.x;
    if (e < E) atomicAdd(&cnt[dst[e]], 1);
}

__global__ void inv_kernel(const int* __restrict__ cnt, float* __restrict__ inv, int N) {
    int i = blockIdx.x * blockDim.x + threadIdx.x;
    if (i < N) inv[i] = 1.0f / (float)max(cnt[i], 1);
}

// single-block exclusive scan (N <= 1024*chunk)
__global__ void scan_kernel(const int* __restrict__ cnt, int* __restrict__ off, int N) {
    __shared__ int part[1024];
    int tid = threadIdx.x;
    int chunk = (N + 1023) >> 10;
    int start = tid * chunk;
    int end = min(start + chunk, N);
    int s = 0;
    for (int i = start; i < end; i++) s += cnt[i];
    part[tid] = s;
    __syncthreads();
    for (int o = 1; o < 1024; o <<= 1) {
        int t = (tid >= o) ? part[tid - o] : 0;
        __syncthreads();
        part[tid] += t;
        __syncthreads();
    }
    int pre = part[tid] - s;
    for (int i = start; i < end; i++) { off[i] = pre; pre += cnt[i]; }
    if (tid == 1023) off[N] = part[1023];
}

__global__ void fill_csr(const int* __restrict__ src, const int* __restrict__ dst,
                         int* __restrict__ pos, int* __restrict__ csr, int E) {
    int e = blockIdx.x * blockDim.x + threadIdx.x;
    if (e < E) {
        int d = dst[e];
        int p = atomicAdd(&pos[d], 1);
        csr[p] = src[e];
    }
}

__global__ void agg_scatter(const float* __restrict__ PE, const int* __restrict__ hsrc,
                            const int* __restrict__ hdst, float* __restrict__ agg, int E) {
    int e = blockIdx.x * blockDim.x + threadIdx.x;
    if (e >= E) return;
    int s = hsrc[e], d = hdst[e];
    float4 v0 = *(const float4*)(PE + (size_t)s * 8);
    float4 v1 = *(const float4*)(PE + (size_t)s * 8 + 4);
    red4(agg + (size_t)d * 8,     v0);
    red4(agg + (size_t)d * 8 + 4, v1);
}

// WT[n][k] = tf32_round( k < Kl ? Wl[k][n] : Wr[k-Kl][n] )
__global__ void transpose_pack(const float* __restrict__ Wl, const float* __restrict__ Wr,
                               float* __restrict__ WT, int Kl, int Kr) {
    int K = Kl + Kr;
    int idx = blockIdx.x * blockDim.x + threadIdx.x;
    if (idx >= 128 * K) return;
    int n = idx / K, k = idx % K;
    float w = (k < Kl) ? Wl[(size_t)k * 128 + n] : Wr[(size_t)(k - Kl) * 128 + n];
    WT[idx] = __uint_as_float(cvt_tf32(w));
}

__global__ void phi_kernel(const float* __restrict__ agg,
                           const float* __restrict__ W1, const float* __restrict__ b1,
                           const float* __restrict__ W2, const float* __restrict__ b2,
                           float* __restrict__ pe, int NTn) {
    __shared__ float sW1[8 * 64];
    __shared__ float sW2[64 * 64];
    __shared__ float sb1[64], sb2[64];
    __shared__ float hid[4][64];
    int tid = threadIdx.x;
    for (int i = tid; i < 512;  i += 256) sW1[i] = W1[i];
    for (int i = tid; i < 4096; i += 256) sW2[i] = W2[i];
    if (tid < 64) { sb1[tid] = b1[tid]; sb2[tid] = b2[tid]; }
    __syncthreads();
    int r = tid >> 6;
    int j = tid & 63;
    int row = blockIdx.x * 4 + r;
    if (row < NTn) {
        float a[8];
        #pragma unroll
        for (int k = 0; k < 8; k++) a[k] = agg[(size_t)row * 8 + k];
        float h = sb1[j];
        #pragma unroll
        for (int k = 0; k < 8; k++) h += a[k] * sW1[k * 64 + j];
        hid[r][j] = fmaxf(h, 0.0f);
    }
    __syncthreads();
    if (row < NTn) {
        float o = sb2[j];
        #pragma unroll
        for (int k = 0; k < 64; k++) o += hid[r][k] * sW2[k * 64 + j];
        pe[(size_t)row * 64 + j] = o;
    }
}

// ---------------- CSR mean gather: one warp per dst row ----------------
__global__ void mean_gather(const float* __restrict__ x, int srcBase,
                            const int* __restrict__ csr, const int* __restrict__ off,
                            const float* __restrict__ inv, float* __restrict__ out, int N)
{
    int w = (blockIdx.x * blockDim.x + threadIdx.x) >> 5;
    if (w >= N) return;
    int lane = threadIdx.x & 31;
    int s0 = off[w], s1 = off[w + 1];
    float4 acc = make_float4(0.f, 0.f, 0.f, 0.f);
    int i = s0;
    for (; i + 2 <= s1; i += 2) {
        int sa = __ldg(csr + i), sb = __ldg(csr + i + 1);
        float4 va = *(const float4*)(x + (size_t)(srcBase + sa) * CC + lane * 4);
        float4 vb = *(const float4*)(x + (size_t)(srcBase + sb) * CC + lane * 4);
        acc.x += va.x + vb.x; acc.y += va.y + vb.y;
        acc.z += va.z + vb.z; acc.w += va.w + vb.w;
    }
    if (i < s1) {
        int sa = __ldg(csr + i);
        float4 va = *(const float4*)(x + (size_t)(srcBase + sa) * CC + lane * 4);
        acc.x += va.x; acc.y += va.y; acc.z += va.z; acc.w += va.w;
    }
    float sc = inv[w];
    acc.x *= sc; acc.y *= sc; acc.z *= sc; acc.w *= sc;
    *(float4*)(out + (size_t)w * CC + lane * 4) = acc;
}

// ---------------- tf32 mma.sync GEMM (merged A/B launch) ----------------
// blocks [0,blocksA): A side; [blocksA, ..): B side. Per-side pointers/weights.
#define GEMM_SMEM_F (640 + 2 * 2560 + 2 * 2560)
#define TILE_F 2560          // 128 rows * 20 floats

__device__ __forceinline__ void load_tile(
    const float* __restrict__ X0, int K0, const float* __restrict__ X1, int K1,
    const float* __restrict__ WT, int K, int m0, int M, int t,
    uint32_t asAddr, uint32_t bsAddr, int tid)
{
    int kb = t * 16;
    #pragma unroll
    for (int i = 0; i < 2; i++) {
        int f = i * 256 + tid;
        int row = f >> 2, q = f & 3;
        int kk = kb + q * 4;
        bool pred = (m0 + row) < M;
        const float* src = (kk < K0)
            ? X0 + (size_t)(m0 + row) * K0 + kk
            : X1 + (size_t)(m0 + row) * K1 + (kk - K0);
        cpasync16(asAddr + (uint32_t)(row * 20 + q * 4) * 4, src, pred);
    }
    #pragma unroll
    for (int i = 0; i < 2; i++) {
        int f = i * 256 + tid;
        int n = f >> 2, q = f & 3;
        cpasync16(bsAddr + (uint32_t)(n * 20 + q * 4) * 4,
                  WT + (size_t)n * K + kb + q * 4, true);
    }
    CP_COMMIT();
}

template<bool DO_LN>
__global__ void __launch_bounds__(256, 2)
gemm_mma(const float* X0a, const float* X0b, int K0,
         const float* X1a, const float* X1b, int K1,
         const float* WTa, const float* WTb, int K,
         const float* biasA, const float* biasB,
         const float* gamA, const float* betA,
         const float* gamB, const float* betB,
         float* outA, float* outB, int Ma, int Mb, int blocksA)
{
    extern __shared__ float sm[];
    float* s_bias  = sm;
    float* s_gamma = sm + 128;
    float* s_beta  = sm + 256;
    float* s_sum   = sm + 384;
    float* s_ss    = sm + 512;
    float* As      = sm + 640;
    float* Bs      = As + 2 * TILE_F;

    bool isB = (int)blockIdx.x >= blocksA;
    const float* X0   = isB ? X0b  : X0a;
    const float* X1   = isB ? X1b  : X1a;
    const float* WT   = isB ? WTb  : WTa;
    const float* bias = isB ? biasB : biasA;
    const float* gamma = isB ? gamB : gamA;
    const float* beta  = isB ? betB : betA;
    float* out = isB ? outB : outA;
    int M  = isB ? Mb : Ma;
    int m0 = (isB ? ((int)blockIdx.x - blocksA) : (int)blockIdx.x) * 128;

    int tid  = threadIdx.x;
    int lane = tid & 31;
    int warp = tid >> 5;
    int wm = warp & 3;
    int wn = warp >> 2;

    if (tid < 128) {
        s_bias[tid] = bias[tid];
        if (DO_LN) {
            s_gamma[tid] = gamma[tid];
            s_beta[tid]  = beta[tid];
            s_sum[tid] = 0.0f;
            s_ss[tid]  = 0.0f;
        }
    }

    uint32_t asAddr = smem_u32(As);
    uint32_t bsAddr = smem_u32(Bs);

    float c[2][8][4];
    #pragma unroll
    for (int mt = 0; mt < 2; mt++)
        #pragma unroll
        for (int nt = 0; nt < 8; nt++)
            #pragma unroll
            for (int j = 0; j < 4; j++) c[mt][nt][j] = 0.0f;

    const int T = K / 16;
    load_tile(X0, K0, X1, K1, WT, K, m0, M, 0, asAddr, bsAddr, tid);
    load_tile(X0, K0, X1, K1, WT, K, m0, M, 1, asAddr + TILE_F * 4, bsAddr + TILE_F * 4, tid);

    for (int t = 0; t < T; t++) {
        if (t + 1 < T) asm volatile("cp.async.wait_group 1;" ::: "memory");
        else           asm volatile("cp.async.wait_group 0;" ::: "memory");
        __syncthreads();

        const float* Ab = As + (t & 1) * TILE_F;
        const float* Bb = Bs + (t & 1) * TILE_F;
        #pragma unroll
        for (int ks = 0; ks < 2; ks++) {
            int k0 = ks * 8 + (lane & 3);
            uint32_t a[2][4];
            #pragma unroll
            for (int mt = 0; mt < 2; mt++) {
                int rb = wm * 32 + mt * 16 + (lane >> 2);
                a[mt][0] = cvt_tf32(Ab[rb * 20 + k0]);
                a[mt][1] = cvt_tf32(Ab[(rb + 8) * 20 + k0]);
                a[mt][2] = cvt_tf32(Ab[rb * 20 + k0 + 4]);
                a[mt][3] = cvt_tf32(Ab[(rb + 8) * 20 + k0 + 4]);
            }
            #pragma unroll
            for (int nt = 0; nt < 8; nt++) {
                int nb = wn * 64 + nt * 8 + (lane >> 2);
                uint32_t b0 = __float_as_uint(Bb[nb * 20 + k0]);
                uint32_t b1 = __float_as_uint(Bb[nb * 20 + k0 + 4]);
                mma_tf32(c[0][nt], a[0], b0, b1);
                mma_tf32(c[1][nt], a[1], b0, b1);
            }
        }
        __syncthreads();
        if (t + 2 < T)
            load_tile(X0, K0, X1, K1, WT, K, m0, M, t + 2,
                      asAddr + (uint32_t)(t & 1) * TILE_F * 4,
                      bsAddr + (uint32_t)(t & 1) * TILE_F * 4, tid);
    }

    // ---- add bias ----
    #pragma unroll
    for (int nt = 0; nt < 8; nt++) {
        int col = wn * 64 + nt * 8 + 2 * (lane & 3);
        float bx = s_bias[col], by = s_bias[col + 1];
        #pragma unroll
        for (int mt = 0; mt < 2; mt++) {
            c[mt][nt][0] += bx; c[mt][nt][1] += by;
            c[mt][nt][2] += bx; c[mt][nt][3] += by;
        }
    }

    if (!DO_LN) {
        #pragma unroll
        for (int mt = 0; mt < 2; mt++)
            #pragma unroll
            for (int h = 0; h < 2; h++) {
                int row = m0 + wm * 32 + mt * 16 + (lane >> 2) + h * 8;
                if (row < M) {
                    #pragma unroll
                    for (int nt = 0; nt < 8; nt++) {
                        int col = wn * 64 + nt * 8 + 2 * (lane & 3);
                        float2 o = make_float2(c[mt][nt][h * 2], c[mt][nt][h * 2 + 1]);
                        *(float2*)(out + (size_t)row * 128 + col) = o;
                    }
                }
            }
        return;
    }

    // ---- LayerNorm + ReLU ----
    #pragma unroll
    for (int mt = 0; mt < 2; mt++)
        #pragma unroll
        for (int h = 0; h < 2; h++) {
            float s = 0.f, q = 0.f;
            #pragma unroll
            for (int nt = 0; nt < 8; nt++) {
                float v0 = c[mt][nt][h * 2], v1 = c[mt][nt][h * 2 + 1];
                s += v0 + v1;
                q += v0 * v0 + v1 * v1;
            }
            s += __shfl_xor_sync(0xffffffffu, s, 1);
            s += __shfl_xor_sync(0xffffffffu, s, 2);
            q += __shfl_xor_sync(0xffffffffu, q, 1);
            q += __shfl_xor_sync(0xffffffffu, q, 2);
            if ((lane & 3) == 0) {
                int rl = wm * 32 + mt * 16 + (lane >> 2) + h * 8;
                atomicAdd(&s_sum[rl], s);
                atomicAdd(&s_ss[rl], q);
            }
        }
    __syncthreads();
    #pragma unroll
    for (int mt = 0; mt < 2; mt++)
        #pragma unroll
        for (int h = 0; h < 2; h++) {
            int rl = wm * 32 + mt * 16 + (lane >> 2) + h * 8;
            int row = m0 + rl;
            float mu   = s_sum[rl] * (1.0f / 128.0f);
            float var  = s_ss[rl] * (1.0f / 128.0f) - mu * mu;
            float rstd = rsqrtf(var + 1e-5f);
            if (row < M) {
                #pragma unroll
                for (int nt = 0; nt < 8; nt++) {
                    int col = wn * 64 + nt * 8 + 2 * (lane & 3);
                    float2 o;
                    o.x = fmaxf((c[mt][nt][h * 2]     - mu) * rstd * s_gamma[col]     + s_beta[col],     0.f);
                    o.y = fmaxf((c[mt][nt][h * 2 + 1] - mu) * rstd * s_gamma[col + 1] + s_beta[col + 1], 0.f);
                    *(float2*)(out + (size_t)row * 128 + col) = o;
                }
            }
        }
}

// ---------------- launch ----------------
extern "C" void kernel_launch(void* const* d_in, const int* in_sizes, int n_in,
                              void* d_out, int out_size)
{
    const float* xA     = (const float*)d_in[0];
    const float* xB     = (const float*)d_in[1];
    const float* PE     = (const float*)d_in[2];
    const int*   edgeAB = (const int*)  d_in[3];
    const int*   edgeBA = (const int*)  d_in[4];
    const int*   hedge  = (const int*)  d_in[5];
    const float* sWl    = (const float*)d_in[6];
    const float* sbl    = (const float*)d_in[7];
    const float* sWr    = (const float*)d_in[8];
    const float* lng    = (const float*)d_in[9];
    const float* lnb    = (const float*)d_in[10];
    const float* pW1    = (const float*)d_in[11];
    const float* pb1    = (const float*)d_in[12];
    const float* pW2    = (const float*)d_in[13];
    const float* pb2    = (const float*)d_in[14];
    const float* peW    = (const float*)d_in[15];
    const float* peb    = (const float*)d_in[16];
    float* out = (float*)d_out;

    float *agg, *pe, *lin, *m, *cur, *invA, *invB, *WTpe, *WTsage;
    int *cntA, *cntB, *offA, *offB, *csrAB, *csrBA;
    cudaGetSymbolAddress((void**)&agg,    g_agg);
    cudaGetSymbolAddress((void**)&pe,     g_pe);
    cudaGetSymbolAddress((void**)&lin,    g_lin);
    cudaGetSymbolAddress((void**)&m,      g_m);
    cudaGetSymbolAddress((void**)&cur,    g_cur);
    cudaGetSymbolAddress((void**)&invA,   g_invA);
    cudaGetSymbolAddress((void**)&invB,   g_invB);
    cudaGetSymbolAddress((void**)&cntA,   g_cntA);
    cudaGetSymbolAddress((void**)&cntB,   g_cntB);
    cudaGetSymbolAddress((void**)&offA,   g_offA);
    cudaGetSymbolAddress((void**)&offB,   g_offB);
    cudaGetSymbolAddress((void**)&csrAB,  g_csrAB);
    cudaGetSymbolAddress((void**)&csrBA,  g_csrBA);
    cudaGetSymbolAddress((void**)&WTpe,   g_WTpe);
    cudaGetSymbolAddress((void**)&WTsage, g_WTsage);

    // ---- degree counts + inverse + CSR (layer-invariant) ----
    cudaMemsetAsync(cntA, 0, N_A * sizeof(int));
    cudaMemsetAsync(cntB, 0, N_B * sizeof(int));
    count_kernel<<<(NE + 255) / 256, 256>>>(edgeAB + NE, cntB, NE);
    count_kernel<<<(NE + 255) / 256, 256>>>(edgeBA + NE, cntA, NE);
    inv_kernel<<<(N_A + 255) / 256, 256>>>(cntA, invA, N_A);
    inv_kernel<<<(N_B + 255) / 256, 256>>>(cntB, invB, N_B);
    scan_kernel<<<1, 1024>>>(cntA, offA, N_A);
    scan_kernel<<<1, 1024>>>(cntB, offB, N_B);
    // reuse cnt buffers as running positions
    cudaMemcpyAsync(cntA, offA, N_A * sizeof(int), cudaMemcpyDeviceToDevice);
    cudaMemcpyAsync(cntB, offB, N_B * sizeof(int), cudaMemcpyDeviceToDevice);
    fill_csr<<<(NE + 255) / 256, 256>>>(edgeAB, edgeAB + NE, cntB, csrAB, NE);
    fill_csr<<<(NE + 255) / 256, 256>>>(edgeBA, edgeBA + NE, cntA, csrBA, NE);

    // ---- homogeneous PE aggregation (layer-invariant) ----
    cudaMemcpyAsync(agg, PE, (size_t)NT * 8 * sizeof(float), cudaMemcpyDeviceToDevice);
    agg_scatter<<<(EHN + 255) / 256, 256>>>(PE, hedge, hedge + EHN, agg, EHN);

    // ---- transpose/pack (+ tf32-round) weights ----
    for (int l = 0; l < 2; l++) {
        transpose_pack<<<(128 * 192 + 255) / 256, 256>>>(
            peW + (size_t)l * 192 * 128, peW, WTpe + (size_t)l * 128 * 192, 192, 0);
        for (int e = 0; e < 2; e++) {
            int li = l * 2 + e;
            transpose_pack<<<(128 * 256 + 255) / 256, 256>>>(
                sWl + (size_t)li * 16384, sWr + (size_t)li * 16384,
                WTsage + (size_t)li * 128 * 256, 128, 128);
        }
    }

    const float* srcA = xA;
    const float* srcB = xB;
    const int blocksA = (N_A + 127) / 128;        // 391
    dim3 gGrid(2 * blocksA);                      // merged A+B launch
    size_t gsm = GEMM_SMEM_F * sizeof(float);
    float* linB = lin + (size_t)N_A * CC;
    float* mB   = m   + (size_t)N_A * CC;

    for (int l = 0; l < 2; l++) {
        phi_kernel<<<(NT + 3) / 4, 256>>>(agg, pW1 + l * 512, pb1 + l * 64,
                                          pW2 + l * 4096, pb2 + l * 64, pe, NT);

        // pe-linear (merged): lin = [x | pe] @ pe_W[l] + pe_b[l]   (K = 192)
        const float* wt = WTpe + (size_t)l * 128 * 192;
        gemm_mma<false><<<gGrid, 256, gsm>>>(
            srcA, srcB, 128,
            pe, pe + (size_t)N_A * 64, 64,
            wt, wt, 192,
            peb + l * 128, peb + l * 128,
            nullptr, nullptr, nullptr, nullptr,
            lin, linB, N_A, N_B, blocksA);

        // CSR mean gather (A gets means of B-sources; B gets means of A-sources)
        mean_gather<<<(N_A * 32 + 255) / 256, 256>>>(lin, N_A, csrBA, offA, invA, m,  N_A);
        mean_gather<<<(N_B * 32 + 255) / 256, 256>>>(lin, 0,   csrAB, offB, invB, mB, N_B);

        float* outA = (l == 1) ? out                    : cur;
        float* outB = (l == 1) ? out + (size_t)N_A * CC : cur + (size_t)N_A * CC;

        // SAGE + LN + ReLU (merged, K = 256). A-update: weights idx1, LN idx0; B: idx0/idx1.
        gemm_mma<true><<<gGrid, 256, gsm>>>(
            m, mB, 128,
            lin, linB, 128,
            WTsage + (size_t)(l * 2 + 1) * 128 * 256,
            WTsage + (size_t)(l * 2 + 0) * 128 * 256, 256,
            sbl + (l * 2 + 1) * 128, sbl + (l * 2 + 0) * 128,
            lng + (l * 2 + 0) * 128, lnb + (l * 2 + 0) * 128,
            lng + (l * 2 + 1) * 128, lnb + (l * 2 + 1) * 128,
            outA, outB, N_A, N_B, blocksA);

        srcA = cur;
        srcB = cur + (size_t)N_A * CC;
    }
}

// round 5
// speedup vs baseline: 2.3393x; 1.3831x over previous
#include <cuda_runtime.h>
#include <cuda_bf16.h>
#include <math.h>
#include <stdint.h>

#define N_A 50000
#define N_B 50000
#define NT  100000
#define NE  800000
#define EHN 1600000
#define CC  128

// ---------------- device scratch (static, no allocation) ----------------
__device__ float g_agg [NT * 8];
__device__ float g_hid [2 * NT * 64];  // relu(agg@W1+b1) per layer (layer-invariant agg)
__device__ float g_lin [NT * CC];      // A rows [0,N_A), B rows [N_A,NT)
__device__ float g_m   [NT * CC];
__device__ float g_cur [NT * CC];
__device__ float g_invA[N_A];
__device__ float g_invB[N_B];
__device__ int   g_cntA[N_A];
__device__ int   g_cntB[N_B];
__device__ int   g_offA[N_A + 1];
__device__ int   g_offB[N_B + 1];
__device__ int   g_csrAB[NE];          // src(A) ids grouped by dst(B)
__device__ int   g_csrBA[NE];          // src(B) ids grouped by dst(A)
__device__ float g_Wc   [2 * 64 * 128];   // W2 @ peW[128:192] per layer
__device__ float g_bc   [2 * 128];        // pe_b + b2 @ peW[128:192]
__device__ float g_WTpe  [2 * 128 * 192];
__device__ float g_WTsage[4 * 128 * 256];

// ---------------- helpers ----------------
__device__ __forceinline__ uint32_t smem_u32(const void* p) {
    uint32_t a;
    asm("{ .reg .u64 t; cvta.to.shared.u64 t, %1; cvt.u32.u64 %0, t; }" : "=r"(a) : "l"(p));
    return a;
}

__device__ __forceinline__ uint32_t cvt_tf32(float f) {
    uint32_t r;
    asm("cvt.rna.tf32.f32 %0, %1;" : "=r"(r) : "f"(f));
    return r;
}

__device__ __forceinline__ void mma_tf32(float c[4], const uint32_t a[4],
                                         uint32_t b0, uint32_t b1) {
    asm volatile(
        "mma.sync.aligned.m16n8k8.row.col.f32.tf32.tf32.f32 "
        "{%0,%1,%2,%3}, {%4,%5,%6,%7}, {%8,%9}, {%0,%1,%2,%3};"
        : "+f"(c[0]), "+f"(c[1]), "+f"(c[2]), "+f"(c[3])
        : "r"(a[0]), "r"(a[1]), "r"(a[2]), "r"(a[3]), "r"(b0), "r"(b1));
}

__device__ __forceinline__ void cpasync16(uint32_t daddr, const float* g, bool pred) {
    int sz = pred ? 16 : 0;
    asm volatile("cp.async.cg.shared.global [%0], [%1], 16, %2;"
                 :: "r"(daddr), "l"(g), "r"(sz) : "memory");
}
#define CP_COMMIT() asm volatile("cp.async.commit_group;" ::: "memory")

__device__ __forceinline__ void red4(float* addr, float4 v) {
    asm volatile("red.global.add.v4.f32 [%0], {%1,%2,%3,%4};"
                 :: "l"(addr), "f"(v.x), "f"(v.y), "f"(v.z), "f"(v.w) : "memory");
}

// ---------------- graph preprocessing ----------------
__global__ void count_kernel(const int* __restrict__ dst, int* __restrict__ cnt, int E) {
    int e = blockIdx.x * blockDim.x + threadIdx.x;
    if (e < E) atomicAdd(&cnt[dst[e]], 1);
}

__global__ void inv_kernel(const int* __restrict__ cnt, float* __restrict__ inv, int N) {
    int i = blockIdx.x * blockDim.x + threadIdx.x;
    if (i < N) inv[i] = 1.0f / (float)max(cnt[i], 1);
}

__global__ void scan_kernel(const int* __restrict__ cnt, int* __restrict__ off, int N) {
    __shared__ int part[1024];
    int tid = threadIdx.x;
    int chunk = (N + 1023) >> 10;
    int start = tid * chunk;
    int end = min(start + chunk, N);
    int s = 0;
    for (int i = start; i < end; i++) s += cnt[i];
    part[tid] = s;
    __syncthreads();
    for (int o = 1; o < 1024; o <<= 1) {
        int t = (tid >= o) ? part[tid - o] : 0;
        __syncthreads();
        part[tid] += t;
        __syncthreads();
    }
    int pre = part[tid] - s;
    for (int i = start; i < end; i++) { off[i] = pre; pre += cnt[i]; }
    if (tid == 1023) off[N] = part[1023];
}

__global__ void fill_csr(const int* __restrict__ src, const int* __restrict__ dst,
                         int* __restrict__ pos, int* __restrict__ csr, int E) {
    int e = blockIdx.x * blockDim.x + threadIdx.x;
    if (e < E) {
        int d = dst[e];
        int p = atomicAdd(&pos[d], 1);
        csr[p] = src[e];
    }
}

__global__ void agg_scatter(const float* __restrict__ PE, const int* __restrict__ hsrc,
                            const int* __restrict__ hdst, float* __restrict__ agg, int E) {
    int e = blockIdx.x * blockDim.x + threadIdx.x;
    if (e >= E) return;
    int s = hsrc[e], d = hdst[e];
    float4 v0 = *(const float4*)(PE + (size_t)s * 8);
    float4 v1 = *(const float4*)(PE + (size_t)s * 8 + 4);
    red4(agg + (size_t)d * 8,     v0);
    red4(agg + (size_t)d * 8 + 4, v1);
}

// Wc[i][j] = sum_p W2[i][p] * peWpe[p][j]   (i<64, j<128)
__global__ void fold_w(const float* __restrict__ W2, const float* __restrict__ peWpe,
                       float* __restrict__ Wc) {
    int idx = blockIdx.x * blockDim.x + threadIdx.x;
    if (idx >= 64 * 128) return;
    int i = idx >> 7, j = idx & 127;
    float s = 0.0f;
    #pragma unroll 8
    for (int p = 0; p < 64; p++) s += W2[i * 64 + p] * peWpe[p * 128 + j];
    Wc[idx] = s;
}

// bc[j] = peb[j] + sum_p b2[p] * peWpe[p][j]
__global__ void fold_b(const float* __restrict__ b2, const float* __restrict__ peWpe,
                       const float* __restrict__ peb, float* __restrict__ bc) {
    int j = threadIdx.x;
    float s = peb[j];
    #pragma unroll 8
    for (int p = 0; p < 64; p++) s += b2[p] * peWpe[p * 128 + j];
    bc[j] = s;
}

// WT[n][k] = tf32_round( k < Kl ? Wl[k][n] : Wr[k-Kl][n] )
__global__ void transpose_pack(const float* __restrict__ Wl, const float* __restrict__ Wr,
                               float* __restrict__ WT, int Kl, int Kr) {
    int K = Kl + Kr;
    int idx = blockIdx.x * blockDim.x + threadIdx.x;
    if (idx >= 128 * K) return;
    int n = idx / K, k = idx % K;
    float w = (k < Kl) ? Wl[(size_t)k * 128 + n] : Wr[(size_t)(k - Kl) * 128 + n];
    WT[idx] = __uint_as_float(cvt_tf32(w));
}

// hid = relu(agg @ W1 + b1)   [NT,8] -> [NT,64]
__global__ void hid_kernel(const float* __restrict__ agg,
                           const float* __restrict__ W1, const float* __restrict__ b1,
                           float* __restrict__ hid, int NTn) {
    __shared__ float sW1[512];
    __shared__ float sb1[64];
    int tid = threadIdx.x;
    for (int i = tid; i < 512; i += 256) sW1[i] = W1[i];
    if (tid < 64) sb1[tid] = b1[tid];
    __syncthreads();
    int r = tid >> 6, j = tid & 63;
    int row = blockIdx.x * 4 + r;
    if (row < NTn) {
        float a[8];
        #pragma unroll
        for (int k = 0; k < 8; k++) a[k] = agg[(size_t)row * 8 + k];
        float h = sb1[j];
        #pragma unroll
        for (int k = 0; k < 8; k++) h += a[k] * sW1[k * 64 + j];
        hid[(size_t)row * 64 + j] = fmaxf(h, 0.0f);
    }
}

// ---------------- merged CSR mean gather: one warp per dst row (A then B) ----------------
__global__ void mean_gather2(const float* __restrict__ lin,
                             const int* __restrict__ csrBA, const int* __restrict__ offA,
                             const float* __restrict__ invA,
                             const int* __restrict__ csrAB, const int* __restrict__ offB,
                             const float* __restrict__ invB,
                             float* __restrict__ m)
{
    int w = (blockIdx.x * blockDim.x + threadIdx.x) >> 5;
    if (w >= NT) return;
    int lane = threadIdx.x & 31;
    const int* csr; const int* off; const float* inv; int srcBase, r;
    if (w < N_A) { csr = csrBA; off = offA; inv = invA; srcBase = N_A; r = w; }
    else         { csr = csrAB; off = offB; inv = invB; srcBase = 0;   r = w - N_A; }
    int s0 = off[r], s1 = off[r + 1];
    float4 acc = make_float4(0.f, 0.f, 0.f, 0.f);
    int i = s0;
    for (; i + 4 <= s1; i += 4) {
        int i0 = __ldg(csr + i),     i1 = __ldg(csr + i + 1);
        int i2 = __ldg(csr + i + 2), i3 = __ldg(csr + i + 3);
        float4 v0 = *(const float4*)(lin + (size_t)(srcBase + i0) * CC + lane * 4);
        float4 v1 = *(const float4*)(lin + (size_t)(srcBase + i1) * CC + lane * 4);
        float4 v2 = *(const float4*)(lin + (size_t)(srcBase + i2) * CC + lane * 4);
        float4 v3 = *(const float4*)(lin + (size_t)(srcBase + i3) * CC + lane * 4);
        acc.x += (v0.x + v1.x) + (v2.x + v3.x);
        acc.y += (v0.y + v1.y) + (v2.y + v3.y);
        acc.z += (v0.z + v1.z) + (v2.z + v3.z);
        acc.w += (v0.w + v1.w) + (v2.w + v3.w);
    }
    for (; i < s1; i++) {
        int i0 = __ldg(csr + i);
        float4 v0 = *(const float4*)(lin + (size_t)(srcBase + i0) * CC + lane * 4);
        acc.x += v0.x; acc.y += v0.y; acc.z += v0.z; acc.w += v0.w;
    }
    float sc = inv[r];
    acc.x *= sc; acc.y *= sc; acc.z *= sc; acc.w *= sc;
    *(float4*)(m + (size_t)w * CC + lane * 4) = acc;
}

// ---------------- tf32 mma.sync GEMM (merged A/B launch) ----------------
#define GEMM_SMEM_F (640 + 2 * 2560 + 2 * 2560)
#define TILE_F 2560

__device__ __forceinline__ void load_tile(
    const float* __restrict__ X0, int K0, const float* __restrict__ X1, int K1,
    const float* __restrict__ WT, int K, int m0, int M, int t,
    uint32_t asAddr, uint32_t bsAddr, int tid)
{
    int kb = t * 16;
    #pragma unroll
    for (int i = 0; i < 2; i++) {
        int f = i * 256 + tid;
        int row = f >> 2, q = f & 3;
        int kk = kb + q * 4;
        bool pred = (m0 + row) < M;
        const float* src = (kk < K0)
            ? X0 + (size_t)(m0 + row) * K0 + kk
            : X1 + (size_t)(m0 + row) * K1 + (kk - K0);
        cpasync16(asAddr + (uint32_t)(row * 20 + q * 4) * 4, src, pred);
    }
    #pragma unroll
    for (int i = 0; i < 2; i++) {
        int f = i * 256 + tid;
        int n = f >> 2, q = f & 3;
        cpasync16(bsAddr + (uint32_t)(n * 20 + q * 4) * 4,
                  WT + (size_t)n * K + kb + q * 4, true);
    }
    CP_COMMIT();
}

template<bool DO_LN>
__global__ void __launch_bounds__(256, 2)
gemm_mma(const float* X0a, const float* X0b, int K0,
         const float* X1a, const float* X1b, int K1,
         const float* WTa, const float* WTb, int K,
         const float* biasA, const float* biasB,
         const float* gamA, const float* betA,
         const float* gamB, const float* betB,
         float* outA, float* outB, int Ma, int Mb, int blocksA)
{
    extern __shared__ float sm[];
    float* s_bias  = sm;
    float* s_gamma = sm + 128;
    float* s_beta  = sm + 256;
    float* s_sum   = sm + 384;
    float* s_ss    = sm + 512;
    float* As      = sm + 640;
    float* Bs      = As + 2 * TILE_F;

    bool isB = (int)blockIdx.x >= blocksA;
    const float* X0   = isB ? X0b  : X0a;
    const float* X1   = isB ? X1b  : X1a;
    const float* WT   = isB ? WTb  : WTa;
    const float* bias = isB ? biasB : biasA;
    const float* gamma = isB ? gamB : gamA;
    const float* beta  = isB ? betB : betA;
    float* out = isB ? outB : outA;
    int M  = isB ? Mb : Ma;
    int m0 = (isB ? ((int)blockIdx.x - blocksA) : (int)blockIdx.x) * 128;

    int tid  = threadIdx.x;
    int lane = tid & 31;
    int warp = tid >> 5;
    int wm = warp & 3;
    int wn = warp >> 2;

    if (tid < 128) {
        s_bias[tid] = bias[tid];
        if (DO_LN) {
            s_gamma[tid] = gamma[tid];
            s_beta[tid]  = beta[tid];
            s_sum[tid] = 0.0f;
            s_ss[tid]  = 0.0f;
        }
    }

    uint32_t asAddr = smem_u32(As);
    uint32_t bsAddr = smem_u32(Bs);

    float c[2][8][4];
    #pragma unroll
    for (int mt = 0; mt < 2; mt++)
        #pragma unroll
        for (int nt = 0; nt < 8; nt++)
            #pragma unroll
            for (int j = 0; j < 4; j++) c[mt][nt][j] = 0.0f;

    const int T = K / 16;
    load_tile(X0, K0, X1, K1, WT, K, m0, M, 0, asAddr, bsAddr, tid);
    load_tile(X0, K0, X1, K1, WT, K, m0, M, 1, asAddr + TILE_F * 4, bsAddr + TILE_F * 4, tid);

    for (int t = 0; t < T; t++) {
        if (t + 1 < T) asm volatile("cp.async.wait_group 1;" ::: "memory");
        else           asm volatile("cp.async.wait_group 0;" ::: "memory");
        __syncthreads();

        const float* Ab = As + (t & 1) * TILE_F;
        const float* Bb = Bs + (t & 1) * TILE_F;
        #pragma unroll
        for (int ks = 0; ks < 2; ks++) {
            int k0 = ks * 8 + (lane & 3);
            uint32_t a[2][4];
            #pragma unroll
            for (int mt = 0; mt < 2; mt++) {
                int rb = wm * 32 + mt * 16 + (lane >> 2);
                a[mt][0] = cvt_tf32(Ab[rb * 20 + k0]);
                a[mt][1] = cvt_tf32(Ab[(rb + 8) * 20 + k0]);
                a[mt][2] = cvt_tf32(Ab[rb * 20 + k0 + 4]);
                a[mt][3] = cvt_tf32(Ab[(rb + 8) * 20 + k0 + 4]);
            }
            #pragma unroll
            for (int nt = 0; nt < 8; nt++) {
                int nb = wn * 64 + nt * 8 + (lane >> 2);
                uint32_t b0 = __float_as_uint(Bb[nb * 20 + k0]);
                uint32_t b1 = __float_as_uint(Bb[nb * 20 + k0 + 4]);
                mma_tf32(c[0][nt], a[0], b0, b1);
                mma_tf32(c[1][nt], a[1], b0, b1);
            }
        }
        __syncthreads();
        if (t + 2 < T)
            load_tile(X0, K0, X1, K1, WT, K, m0, M, t + 2,
                      asAddr + (uint32_t)(t & 1) * TILE_F * 4,
                      bsAddr + (uint32_t)(t & 1) * TILE_F * 4, tid);
    }

    #pragma unroll
    for (int nt = 0; nt < 8; nt++) {
        int col = wn * 64 + nt * 8 + 2 * (lane & 3);
        float bx = s_bias[col], by = s_bias[col + 1];
        #pragma unroll
        for (int mt = 0; mt < 2; mt++) {
            c[mt][nt][0] += bx; c[mt][nt][1] += by;
            c[mt][nt][2] += bx; c[mt][nt][3] += by;
        }
    }

    if (!DO_LN) {
        #pragma unroll
        for (int mt = 0; mt < 2; mt++)
            #pragma unroll
            for (int h = 0; h < 2; h++) {
                int row = m0 + wm * 32 + mt * 16 + (lane >> 2) + h * 8;
                if (row < M) {
                    #pragma unroll
                    for (int nt = 0; nt < 8; nt++) {
                        int col = wn * 64 + nt * 8 + 2 * (lane & 3);
                        float2 o = make_float2(c[mt][nt][h * 2], c[mt][nt][h * 2 + 1]);
                        *(float2*)(out + (size_t)row * 128 + col) = o;
                    }
                }
            }
        return;
    }

    #pragma unroll
    for (int mt = 0; mt < 2; mt++)
        #pragma unroll
        for (int h = 0; h < 2; h++) {
            float s = 0.f, q = 0.f;
            #pragma unroll
            for (int nt = 0; nt < 8; nt++) {
                float v0 = c[mt][nt][h * 2], v1 = c[mt][nt][h * 2 + 1];
                s += v0 + v1;
                q += v0 * v0 + v1 * v1;
            }
            s += __shfl_xor_sync(0xffffffffu, s, 1);
            s += __shfl_xor_sync(0xffffffffu, s, 2);
            q += __shfl_xor_sync(0xffffffffu, q, 1);
            q += __shfl_xor_sync(0xffffffffu, q, 2);
            if ((lane & 3) == 0) {
                int rl = wm * 32 + mt * 16 + (lane >> 2) + h * 8;
                atomicAdd(&s_sum[rl], s);
                atomicAdd(&s_ss[rl], q);
            }
        }
    __syncthreads();
    #pragma unroll
    for (int mt = 0; mt < 2; mt++)
        #pragma unroll
        for (int h = 0; h < 2; h++) {
            int rl = wm * 32 + mt * 16 + (lane >> 2) + h * 8;
            int row = m0 + rl;
            float mu   = s_sum[rl] * (1.0f / 128.0f);
            float var  = s_ss[rl] * (1.0f / 128.0f) - mu * mu;
            float rstd = rsqrtf(var + 1e-5f);
            if (row < M) {
                #pragma unroll
                for (int nt = 0; nt < 8; nt++) {
                    int col = wn * 64 + nt * 8 + 2 * (lane & 3);
                    float2 o;
                    o.x = fmaxf((c[mt][nt][h * 2]     - mu) * rstd * s_gamma[col]     + s_beta[col],     0.f);
                    o.y = fmaxf((c[mt][nt][h * 2 + 1] - mu) * rstd * s_gamma[col + 1] + s_beta[col + 1], 0.f);
                    *(float2*)(out + (size_t)row * 128 + col) = o;
                }
            }
        }
}

// ---------------- launch ----------------
extern "C" void kernel_launch(void* const* d_in, const int* in_sizes, int n_in,
                              void* d_out, int out_size)
{
    const float* xA     = (const float*)d_in[0];
    const float* xB     = (const float*)d_in[1];
    const float* PE     = (const float*)d_in[2];
    const int*   edgeAB = (const int*)  d_in[3];
    const int*   edgeBA = (const int*)  d_in[4];
    const int*   hedge  = (const int*)  d_in[5];
    const float* sWl    = (const float*)d_in[6];
    const float* sbl    = (const float*)d_in[7];
    const float* sWr    = (const float*)d_in[8];
    const float* lng    = (const float*)d_in[9];
    const float* lnb    = (const float*)d_in[10];
    const float* pW1    = (const float*)d_in[11];
    const float* pb1    = (const float*)d_in[12];
    const float* pW2    = (const float*)d_in[13];
    const float* pb2    = (const float*)d_in[14];
    const float* peW    = (const float*)d_in[15];
    const float* peb    = (const float*)d_in[16];
    float* out = (float*)d_out;

    float *agg, *hid, *lin, *m, *cur, *invA, *invB, *Wc, *bc, *WTpe, *WTsage;
    int *cntA, *cntB, *offA, *offB, *csrAB, *csrBA;
    cudaGetSymbolAddress((void**)&agg,    g_agg);
    cudaGetSymbolAddress((void**)&hid,    g_hid);
    cudaGetSymbolAddress((void**)&lin,    g_lin);
    cudaGetSymbolAddress((void**)&m,      g_m);
    cudaGetSymbolAddress((void**)&cur,    g_cur);
    cudaGetSymbolAddress((void**)&invA,   g_invA);
    cudaGetSymbolAddress((void**)&invB,   g_invB);
    cudaGetSymbolAddress((void**)&cntA,   g_cntA);
    cudaGetSymbolAddress((void**)&cntB,   g_cntB);
    cudaGetSymbolAddress((void**)&offA,   g_offA);
    cudaGetSymbolAddress((void**)&offB,   g_offB);
    cudaGetSymbolAddress((void**)&csrAB,  g_csrAB);
    cudaGetSymbolAddress((void**)&csrBA,  g_csrBA);
    cudaGetSymbolAddress((void**)&Wc,     g_Wc);
    cudaGetSymbolAddress((void**)&bc,     g_bc);
    cudaGetSymbolAddress((void**)&WTpe,   g_WTpe);
    cudaGetSymbolAddress((void**)&WTsage, g_WTsage);

    // side stream for prep work (created per call; joined before any consumer)
    cudaStream_t s2;
    cudaStreamCreateWithFlags(&s2, cudaStreamNonBlocking);
    cudaEvent_t e0, e_wt, e_csr;
    cudaEventCreateWithFlags(&e0,    cudaEventDisableTiming);
    cudaEventCreateWithFlags(&e_wt,  cudaEventDisableTiming);
    cudaEventCreateWithFlags(&e_csr, cudaEventDisableTiming);

    // fork
    cudaEventRecord(e0, 0);
    cudaStreamWaitEvent(s2, e0, 0);

    // ---- s2: weight folds + transposes, then CSR/degree chain ----
    for (int l = 0; l < 2; l++) {
        const float* peWpe = peW + (size_t)l * 192 * 128 + 128 * 128;
        fold_w<<<32, 256, 0, s2>>>(pW2 + l * 4096, peWpe, Wc + (size_t)l * 64 * 128);
        fold_b<<<1, 128, 0, s2>>>(pb2 + l * 64, peWpe, peb + l * 128, bc + l * 128);
        transpose_pack<<<(128 * 192 + 255) / 256, 256, 0, s2>>>(
            peW + (size_t)l * 192 * 128, Wc + (size_t)l * 64 * 128,
            WTpe + (size_t)l * 128 * 192, 128, 64);
        for (int e = 0; e < 2; e++) {
            int li = l * 2 + e;
            transpose_pack<<<(128 * 256 + 255) / 256, 256, 0, s2>>>(
                sWl + (size_t)li * 16384, sWr + (size_t)li * 16384,
                WTsage + (size_t)li * 128 * 256, 128, 128);
        }
    }
    cudaEventRecord(e_wt, s2);

    cudaMemsetAsync(cntA, 0, N_A * sizeof(int), s2);
    cudaMemsetAsync(cntB, 0, N_B * sizeof(int), s2);
    count_kernel<<<(NE + 255) / 256, 256, 0, s2>>>(edgeAB + NE, cntB, NE);
    count_kernel<<<(NE + 255) / 256, 256, 0, s2>>>(edgeBA + NE, cntA, NE);
    inv_kernel<<<(N_A + 255) / 256, 256, 0, s2>>>(cntA, invA, N_A);
    inv_kernel<<<(N_B + 255) / 256, 256, 0, s2>>>(cntB, invB, N_B);
    scan_kernel<<<1, 1024, 0, s2>>>(cntA, offA, N_A);
    scan_kernel<<<1, 1024, 0, s2>>>(cntB, offB, N_B);
    cudaMemcpyAsync(cntA, offA, N_A * sizeof(int), cudaMemcpyDeviceToDevice, s2);
    cudaMemcpyAsync(cntB, offB, N_B * sizeof(int), cudaMemcpyDeviceToDevice, s2);
    fill_csr<<<(NE + 255) / 256, 256, 0, s2>>>(edgeAB, edgeAB + NE, cntB, csrAB, NE);
    fill_csr<<<(NE + 255) / 256, 256, 0, s2>>>(edgeBA, edgeBA + NE, cntA, csrBA, NE);
    cudaEventRecord(e_csr, s2);

    // ---- default stream: critical path ----
    cudaMemcpyAsync(agg, PE, (size_t)NT * 8 * sizeof(float), cudaMemcpyDeviceToDevice);
    agg_scatter<<<(EHN + 255) / 256, 256>>>(PE, hedge, hedge + EHN, agg, EHN);
    hid_kernel<<<(NT + 3) / 4, 256>>>(agg, pW1,       pb1,      hid,                      NT);
    hid_kernel<<<(NT + 3) / 4, 256>>>(agg, pW1 + 512, pb1 + 64, hid + (size_t)NT * 64,    NT);

    cudaStreamWaitEvent(0, e_wt, 0);     // weights ready

    const float* srcA = xA;
    const float* srcB = xB;
    const int blocksA = (N_A + 127) / 128;
    dim3 gGrid(2 * blocksA);
    size_t gsm = GEMM_SMEM_F * sizeof(float);
    float* linB = lin + (size_t)N_A * CC;
    float* mB   = m   + (size_t)N_A * CC;
    bool joined_csr = false;

    for (int l = 0; l < 2; l++) {
        const float* hl = hid + (size_t)l * NT * 64;

        // pe-linear (phi layer-2 folded): lin = [x | relu(h)] @ WTpe^T + bc
        gemm_mma<false><<<gGrid, 256, gsm>>>(
            srcA, srcB, 128,
            hl, hl + (size_t)N_A * 64, 64,
            WTpe + (size_t)l * 128 * 192, WTpe + (size_t)l * 128 * 192, 192,
            bc + l * 128, bc + l * 128,
            nullptr, nullptr, nullptr, nullptr,
            lin, linB, N_A, N_B, blocksA);

        if (!joined_csr) { cudaStreamWaitEvent(0, e_csr, 0); joined_csr = true; }

        // merged CSR mean gather (A-dst from B-src, B-dst from A-src)
        mean_gather2<<<(NT * 32 + 255) / 256, 256>>>(lin, csrBA, offA, invA,
                                                     csrAB, offB, invB, m);

        float* outA = (l == 1) ? out                    : cur;
        float* outB = (l == 1) ? out + (size_t)N_A * CC : cur + (size_t)N_A * CC;

        // SAGE + LN + ReLU (merged). A-update: weights idx1, LN idx0; B: idx0/idx1.
        gemm_mma<true><<<gGrid, 256, gsm>>>(
            m, mB, 128,
            lin, linB, 128,
            WTsage + (size_t)(l * 2 + 1) * 128 * 256,
            WTsage + (size_t)(l * 2 + 0) * 128 * 256, 256,
            sbl + (l * 2 + 1) * 128, sbl + (l * 2 + 0) * 128,
            lng + (l * 2 + 0) * 128, lnb + (l * 2 + 0) * 128,
            lng + (l * 2 + 1) * 128, lnb + (l * 2 + 1) * 128,
            outA, outB, N_A, N_B, blocksA);

        srcA = cur;
        srcB = cur + (size_t)N_A * CC;
    }
    // all s2 work joined via e_wt/e_csr; nothing left pending on s2
}

// round 6
// speedup vs baseline: 2.4055x; 1.0283x over previous
#include <cuda_runtime.h>
#include <cuda_bf16.h>
#include <math.h>
#include <stdint.h>

#define N_A 50000
#define N_B 50000
#define NT  100000
#define NE  800000
#define EHN 1600000
#define CC  128

// ---------------- device scratch (static, no allocation) ----------------
__device__ float g_agg [NT * 8];
__device__ float g_hid [2 * NT * 64];
__device__ float g_lin [NT * CC];          // fp32 (GEMM self-term input)
__device__ __nv_bfloat16 g_lin16[NT * CC]; // bf16 shadow (gather input)
__device__ float g_m   [NT * CC];
__device__ float g_cur [NT * CC];
__device__ float g_invA[N_A];
__device__ float g_invB[N_B];
__device__ int   g_cntA[N_A];
__device__ int   g_cntB[N_B];
__device__ int   g_offA[N_A + 1];
__device__ int   g_offB[N_B + 1];
__device__ int   g_csrAB[NE];
__device__ int   g_csrBA[NE];
__device__ float g_Wc   [2 * 64 * 128];
__device__ float g_bc   [2 * 128];
__device__ float g_WTpe  [2 * 128 * 192];
__device__ float g_WTsage[4 * 128 * 256];

// ---------------- helpers ----------------
__device__ __forceinline__ uint32_t smem_u32(const void* p) {
    uint32_t a;
    asm("{ .reg .u64 t; cvta.to.shared.u64 t, %1; cvt.u32.u64 %0, t; }" : "=r"(a) : "l"(p));
    return a;
}

__device__ __forceinline__ uint32_t cvt_tf32(float f) {
    uint32_t r;
    asm("cvt.rna.tf32.f32 %0, %1;" : "=r"(r) : "f"(f));
    return r;
}

__device__ __forceinline__ void mma_tf32(float c[4], const uint32_t a[4],
                                         uint32_t b0, uint32_t b1) {
    asm volatile(
        "mma.sync.aligned.m16n8k8.row.col.f32.tf32.tf32.f32 "
        "{%0,%1,%2,%3}, {%4,%5,%6,%7}, {%8,%9}, {%0,%1,%2,%3};"
        : "+f"(c[0]), "+f"(c[1]), "+f"(c[2]), "+f"(c[3])
        : "r"(a[0]), "r"(a[1]), "r"(a[2]), "r"(a[3]), "r"(b0), "r"(b1));
}

__device__ __forceinline__ void cpasync16(uint32_t daddr, const float* g, bool pred) {
    int sz = pred ? 16 : 0;
    asm volatile("cp.async.cg.shared.global [%0], [%1], 16, %2;"
                 :: "r"(daddr), "l"(g), "r"(sz) : "memory");
}
#define CP_COMMIT() asm volatile("cp.async.commit_group;" ::: "memory")

__device__ __forceinline__ void red4(float* addr, float4 v) {
    asm volatile("red.global.add.v4.f32 [%0], {%1,%2,%3,%4};"
                 :: "l"(addr), "f"(v.x), "f"(v.y), "f"(v.z), "f"(v.w) : "memory");
}

// ---------------- graph preprocessing ----------------
__global__ void count_kernel(const int* __restrict__ dst, int* __restrict__ cnt, int E) {
    int e = blockIdx.x * blockDim.x + threadIdx.x;
    if (e < E) atomicAdd(&cnt[dst[e]], 1);
}

__global__ void inv_kernel(const int* __restrict__ cnt, float* __restrict__ inv, int N) {
    int i = blockIdx.x * blockDim.x + threadIdx.x;
    if (i < N) inv[i] = 1.0f / (float)max(cnt[i], 1);
}

__global__ void scan_kernel(const int* __restrict__ cnt, int* __restrict__ off, int N) {
    __shared__ int part[1024];
    int tid = threadIdx.x;
    int chunk = (N + 1023) >> 10;
    int start = tid * chunk;
    int end = min(start + chunk, N);
    int s = 0;
    for (int i = start; i < end; i++) s += cnt[i];
    part[tid] = s;
    __syncthreads();
    for (int o = 1; o < 1024; o <<= 1) {
        int t = (tid >= o) ? part[tid - o] : 0;
        __syncthreads();
        part[tid] += t;
        __syncthreads();
    }
    int pre = part[tid] - s;
    for (int i = start; i < end; i++) { off[i] = pre; pre += cnt[i]; }
    if (tid == 1023) off[N] = part[1023];
}

__global__ void fill_csr(const int* __restrict__ src, const int* __restrict__ dst,
                         int* __restrict__ pos, int* __restrict__ csr, int E) {
    int e = blockIdx.x * blockDim.x + threadIdx.x;
    if (e < E) {
        int d = dst[e];
        int p = atomicAdd(&pos[d], 1);
        csr[p] = src[e];
    }
}

__global__ void agg_scatter(const float* __restrict__ PE, const int* __restrict__ hsrc,
                            const int* __restrict__ hdst, float* __restrict__ agg, int E) {
    int e = blockIdx.x * blockDim.x + threadIdx.x;
    if (e >= E) return;
    int s = hsrc[e], d = hdst[e];
    float4 v0 = *(const float4*)(PE + (size_t)s * 8);
    float4 v1 = *(const float4*)(PE + (size_t)s * 8 + 4);
    red4(agg + (size_t)d * 8,     v0);
    red4(agg + (size_t)d * 8 + 4, v1);
}

__global__ void fold_w(const float* __restrict__ W2, const float* __restrict__ peWpe,
                       float* __restrict__ Wc) {
    int idx = blockIdx.x * blockDim.x + threadIdx.x;
    if (idx >= 64 * 128) return;
    int i = idx >> 7, j = idx & 127;
    float s = 0.0f;
    #pragma unroll 8
    for (int p = 0; p < 64; p++) s += W2[i * 64 + p] * peWpe[p * 128 + j];
    Wc[idx] = s;
}

__global__ void fold_b(const float* __restrict__ b2, const float* __restrict__ peWpe,
                       const float* __restrict__ peb, float* __restrict__ bc) {
    int j = threadIdx.x;
    float s = peb[j];
    #pragma unroll 8
    for (int p = 0; p < 64; p++) s += b2[p] * peWpe[p * 128 + j];
    bc[j] = s;
}

__global__ void transpose_pack(const float* __restrict__ Wl, const float* __restrict__ Wr,
                               float* __restrict__ WT, int Kl, int Kr) {
    int K = Kl + Kr;
    int idx = blockIdx.x * blockDim.x + threadIdx.x;
    if (idx >= 128 * K) return;
    int n = idx / K, k = idx % K;
    float w = (k < Kl) ? Wl[(size_t)k * 128 + n] : Wr[(size_t)(k - Kl) * 128 + n];
    WT[idx] = __uint_as_float(cvt_tf32(w));
}

// both layers' hid in one pass over agg
__global__ void hid_kernel2(const float* __restrict__ agg,
                            const float* __restrict__ W1, const float* __restrict__ b1,
                            float* __restrict__ hid, int NTn) {
    __shared__ float sW1[2][512];
    __shared__ float sb1[2][64];
    int tid = threadIdx.x;
    for (int i = tid; i < 512; i += 256) { sW1[0][i] = W1[i]; sW1[1][i] = W1[512 + i]; }
    if (tid < 64) { sb1[0][tid] = b1[tid]; sb1[1][tid] = b1[64 + tid]; }
    __syncthreads();
    int r = tid >> 6, j = tid & 63;
    int row = blockIdx.x * 4 + r;
    if (row < NTn) {
        float a[8];
        #pragma unroll
        for (int k = 0; k < 8; k++) a[k] = agg[(size_t)row * 8 + k];
        #pragma unroll
        for (int l = 0; l < 2; l++) {
            float h = sb1[l][j];
            #pragma unroll
            for (int k = 0; k < 8; k++) h += a[k] * sW1[l][k * 64 + j];
            hid[(size_t)l * NT * 64 + (size_t)row * 64 + j] = fmaxf(h, 0.0f);
        }
    }
}

// ---------------- merged CSR mean gather (bf16 source): one warp per dst row ----------------
__global__ void mean_gather2(const __nv_bfloat16* __restrict__ lin16,
                             const int* __restrict__ csrBA, const int* __restrict__ offA,
                             const float* __restrict__ invA,
                             const int* __restrict__ csrAB, const int* __restrict__ offB,
                             const float* __restrict__ invB,
                             float* __restrict__ m)
{
    int w = (blockIdx.x * blockDim.x + threadIdx.x) >> 5;
    if (w >= NT) return;
    int lane = threadIdx.x & 31;
    const int* csr; const int* off; const float* inv; int srcBase, r;
    if (w < N_A) { csr = csrBA; off = offA; inv = invA; srcBase = N_A; r = w; }
    else         { csr = csrAB; off = offB; inv = invB; srcBase = 0;   r = w - N_A; }
    int s0 = off[r], s1 = off[r + 1];
    float4 acc = make_float4(0.f, 0.f, 0.f, 0.f);
    int i = s0;
    for (; i + 4 <= s1; i += 4) {
        int i0 = __ldg(csr + i),     i1 = __ldg(csr + i + 1);
        int i2 = __ldg(csr + i + 2), i3 = __ldg(csr + i + 3);
        #pragma unroll
        for (int u = 0; u < 4; u++) {
            int sidx = (u == 0) ? i0 : (u == 1) ? i1 : (u == 2) ? i2 : i3;
            const __nv_bfloat162* p = (const __nv_bfloat162*)
                (lin16 + (size_t)(srcBase + sidx) * CC + lane * 4);
            __nv_bfloat162 h0 = p[0], h1 = p[1];
            float2 f0 = __bfloat1622float2(h0);
            float2 f1 = __bfloat1622float2(h1);
            acc.x += f0.x; acc.y += f0.y; acc.z += f1.x; acc.w += f1.y;
        }
    }
    for (; i < s1; i++) {
        int sidx = __ldg(csr + i);
        const __nv_bfloat162* p = (const __nv_bfloat162*)
            (lin16 + (size_t)(srcBase + sidx) * CC + lane * 4);
        __nv_bfloat162 h0 = p[0], h1 = p[1];
        float2 f0 = __bfloat1622float2(h0);
        float2 f1 = __bfloat1622float2(h1);
        acc.x += f0.x; acc.y += f0.y; acc.z += f1.x; acc.w += f1.y;
    }
    float sc = inv[r];
    acc.x *= sc; acc.y *= sc; acc.z *= sc; acc.w *= sc;
    *(float4*)(m + (size_t)w * CC + lane * 4) = acc;
}

// ---------------- tf32 mma.sync GEMM (merged A/B launch) ----------------
#define GEMM_SMEM_F (640 + 2 * 2560 + 2 * 2560)
#define TILE_F 2560

__device__ __forceinline__ void load_tile(
    const float* __restrict__ X0, int K0, const float* __restrict__ X1, int K1,
    const float* __restrict__ WT, int K, int m0, int M, int t,
    uint32_t asAddr, uint32_t bsAddr, int tid)
{
    int kb = t * 16;
    #pragma unroll
    for (int i = 0; i < 2; i++) {
        int f = i * 256 + tid;
        int row = f >> 2, q = f & 3;
        int kk = kb + q * 4;
        bool pred = (m0 + row) < M;
        const float* src = (kk < K0)
            ? X0 + (size_t)(m0 + row) * K0 + kk
            : X1 + (size_t)(m0 + row) * K1 + (kk - K0);
        cpasync16(asAddr + (uint32_t)(row * 20 + q * 4) * 4, src, pred);
    }
    #pragma unroll
    for (int i = 0; i < 2; i++) {
        int f = i * 256 + tid;
        int n = f >> 2, q = f & 3;
        cpasync16(bsAddr + (uint32_t)(n * 20 + q * 4) * 4,
                  WT + (size_t)n * K + kb + q * 4, true);
    }
    CP_COMMIT();
}

template<bool DO_LN>
__global__ void __launch_bounds__(256, 2)
gemm_mma(const float* X0a, const float* X0b, int K0,
         const float* X1a, const float* X1b, int K1,
         const float* WTa, const float* WTb, int K,
         const float* biasA, const float* biasB,
         const float* gamA, const float* betA,
         const float* gamB, const float* betB,
         float* outA, float* outB, __nv_bfloat16* out16,
         int Ma, int Mb, int blocksA)
{
    extern __shared__ float sm[];
    float* s_bias  = sm;
    float* s_gamma = sm + 128;
    float* s_beta  = sm + 256;
    float* s_sum   = sm + 384;
    float* s_ss    = sm + 512;
    float* As      = sm + 640;
    float* Bs      = As + 2 * TILE_F;

    bool isB = (int)blockIdx.x >= blocksA;
    const float* X0   = isB ? X0b  : X0a;
    const float* X1   = isB ? X1b  : X1a;
    const float* WT   = isB ? WTb  : WTa;
    const float* bias = isB ? biasB : biasA;
    const float* gamma = isB ? gamB : gamA;
    const float* beta  = isB ? betB : betA;
    float* out = isB ? outB : outA;
    int M  = isB ? Mb : Ma;
    int mrow0 = (isB ? ((int)blockIdx.x - blocksA) : (int)blockIdx.x) * 128;
    // bf16 shadow offset: rows are globally indexed [A | B]
    size_t row16base = isB ? (size_t)N_A : 0;

    int tid  = threadIdx.x;
    int lane = tid & 31;
    int warp = tid >> 5;
    int wm = warp & 3;
    int wn = warp >> 2;

    if (tid < 128) {
        s_bias[tid] = bias[tid];
        if (DO_LN) {
            s_gamma[tid] = gamma[tid];
            s_beta[tid]  = beta[tid];
            s_sum[tid] = 0.0f;
            s_ss[tid]  = 0.0f;
        }
    }

    uint32_t asAddr = smem_u32(As);
    uint32_t bsAddr = smem_u32(Bs);

    float c[2][8][4];
    #pragma unroll
    for (int mt = 0; mt < 2; mt++)
        #pragma unroll
        for (int nt = 0; nt < 8; nt++)
            #pragma unroll
            for (int j = 0; j < 4; j++) c[mt][nt][j] = 0.0f;

    const int T = K / 16;
    load_tile(X0, K0, X1, K1, WT, K, mrow0, M, 0, asAddr, bsAddr, tid);
    load_tile(X0, K0, X1, K1, WT, K, mrow0, M, 1, asAddr + TILE_F * 4, bsAddr + TILE_F * 4, tid);

    for (int t = 0; t < T; t++) {
        if (t + 1 < T) asm volatile("cp.async.wait_group 1;" ::: "memory");
        else           asm volatile("cp.async.wait_group 0;" ::: "memory");
        __syncthreads();

        const float* Ab = As + (t & 1) * TILE_F;
        const float* Bb = Bs + (t & 1) * TILE_F;
        #pragma unroll
        for (int ks = 0; ks < 2; ks++) {
            int k0 = ks * 8 + (lane & 3);
            uint32_t a[2][4];
            #pragma unroll
            for (int mt = 0; mt < 2; mt++) {
                int rb = wm * 32 + mt * 16 + (lane >> 2);
                a[mt][0] = cvt_tf32(Ab[rb * 20 + k0]);
                a[mt][1] = cvt_tf32(Ab[(rb + 8) * 20 + k0]);
                a[mt][2] = cvt_tf32(Ab[rb * 20 + k0 + 4]);
                a[mt][3] = cvt_tf32(Ab[(rb + 8) * 20 + k0 + 4]);
            }
            #pragma unroll
            for (int nt = 0; nt < 8; nt++) {
                int nb = wn * 64 + nt * 8 + (lane >> 2);
                uint32_t b0 = __float_as_uint(Bb[nb * 20 + k0]);
                uint32_t b1 = __float_as_uint(Bb[nb * 20 + k0 + 4]);
                mma_tf32(c[0][nt], a[0], b0, b1);
                mma_tf32(c[1][nt], a[1], b0, b1);
            }
        }
        __syncthreads();
        if (t + 2 < T)
            load_tile(X0, K0, X1, K1, WT, K, mrow0, M, t + 2,
                      asAddr + (uint32_t)(t & 1) * TILE_F * 4,
                      bsAddr + (uint32_t)(t & 1) * TILE_F * 4, tid);
    }

    #pragma unroll
    for (int nt = 0; nt < 8; nt++) {
        int col = wn * 64 + nt * 8 + 2 * (lane & 3);
        float bx = s_bias[col], by = s_bias[col + 1];
        #pragma unroll
        for (int mt = 0; mt < 2; mt++) {
            c[mt][nt][0] += bx; c[mt][nt][1] += by;
            c[mt][nt][2] += bx; c[mt][nt][3] += by;
        }
    }

    if (!DO_LN) {
        #pragma unroll
        for (int mt = 0; mt < 2; mt++)
            #pragma unroll
            for (int h = 0; h < 2; h++) {
                int rloc = wm * 32 + mt * 16 + (lane >> 2) + h * 8;
                int row = mrow0 + rloc;
                if (row < M) {
                    #pragma unroll
                    for (int nt = 0; nt < 8; nt++) {
                        int col = wn * 64 + nt * 8 + 2 * (lane & 3);
                        float2 o = make_float2(c[mt][nt][h * 2], c[mt][nt][h * 2 + 1]);
                        *(float2*)(out + (size_t)row * 128 + col) = o;
                        __nv_bfloat162 o16 = __float22bfloat162_rn(o);
                        *(__nv_bfloat162*)(out16 + (row16base + row) * 128 + col) = o16;
                    }
                }
            }
        return;
    }

    #pragma unroll
    for (int mt = 0; mt < 2; mt++)
        #pragma unroll
        for (int h = 0; h < 2; h++) {
            float s = 0.f, q = 0.f;
            #pragma unroll
            for (int nt = 0; nt < 8; nt++) {
                float v0 = c[mt][nt][h * 2], v1 = c[mt][nt][h * 2 + 1];
                s += v0 + v1;
                q += v0 * v0 + v1 * v1;
            }
            s += __shfl_xor_sync(0xffffffffu, s, 1);
            s += __shfl_xor_sync(0xffffffffu, s, 2);
            q += __shfl_xor_sync(0xffffffffu, q, 1);
            q += __shfl_xor_sync(0xffffffffu, q, 2);
            if ((lane & 3) == 0) {
                int rl = wm * 32 + mt * 16 + (lane >> 2) + h * 8;
                atomicAdd(&s_sum[rl], s);
                atomicAdd(&s_ss[rl], q);
            }
        }
    __syncthreads();
    #pragma unroll
    for (int mt = 0; mt < 2; mt++)
        #pragma unroll
        for (int h = 0; h < 2; h++) {
            int rl = wm * 32 + mt * 16 + (lane >> 2) + h * 8;
            int row = mrow0 + rl;
            float mu   = s_sum[rl] * (1.0f / 128.0f);
            float var  = s_ss[rl] * (1.0f / 128.0f) - mu * mu;
            float rstd = rsqrtf(var + 1e-5f);
            if (row < M) {
                #pragma unroll
                for (int nt = 0; nt < 8; nt++) {
                    int col = wn * 64 + nt * 8 + 2 * (lane & 3);
                    float2 o;
                    o.x = fmaxf((c[mt][nt][h * 2]     - mu) * rstd * s_gamma[col]     + s_beta[col],     0.f);
                    o.y = fmaxf((c[mt][nt][h * 2 + 1] - mu) * rstd * s_gamma[col + 1] + s_beta[col + 1], 0.f);
                    *(float2*)(out + (size_t)row * 128 + col) = o;
                }
            }
        }
}

// ---------------- launch ----------------
extern "C" void kernel_launch(void* const* d_in, const int* in_sizes, int n_in,
                              void* d_out, int out_size)
{
    const float* xA     = (const float*)d_in[0];
    const float* xB     = (const float*)d_in[1];
    const float* PE     = (const float*)d_in[2];
    const int*   edgeAB = (const int*)  d_in[3];
    const int*   edgeBA = (const int*)  d_in[4];
    const int*   hedge  = (const int*)  d_in[5];
    const float* sWl    = (const float*)d_in[6];
    const float* sbl    = (const float*)d_in[7];
    const float* sWr    = (const float*)d_in[8];
    const float* lng    = (const float*)d_in[9];
    const float* lnb    = (const float*)d_in[10];
    const float* pW1    = (const float*)d_in[11];
    const float* pb1    = (const float*)d_in[12];
    const float* pW2    = (const float*)d_in[13];
    const float* pb2    = (const float*)d_in[14];
    const float* peW    = (const float*)d_in[15];
    const float* peb    = (const float*)d_in[16];
    float* out = (float*)d_out;

    float *agg, *hid, *lin, *m, *cur, *invA, *invB, *Wc, *bc, *WTpe, *WTsage;
    __nv_bfloat16* lin16;
    int *cntA, *cntB, *offA, *offB, *csrAB, *csrBA;
    cudaGetSymbolAddress((void**)&agg,    g_agg);
    cudaGetSymbolAddress((void**)&hid,    g_hid);
    cudaGetSymbolAddress((void**)&lin,    g_lin);
    cudaGetSymbolAddress((void**)&lin16,  g_lin16);
    cudaGetSymbolAddress((void**)&m,      g_m);
    cudaGetSymbolAddress((void**)&cur,    g_cur);
    cudaGetSymbolAddress((void**)&invA,   g_invA);
    cudaGetSymbolAddress((void**)&invB,   g_invB);
    cudaGetSymbolAddress((void**)&cntA,   g_cntA);
    cudaGetSymbolAddress((void**)&cntB,   g_cntB);
    cudaGetSymbolAddress((void**)&offA,   g_offA);
    cudaGetSymbolAddress((void**)&offB,   g_offB);
    cudaGetSymbolAddress((void**)&csrAB,  g_csrAB);
    cudaGetSymbolAddress((void**)&csrBA,  g_csrBA);
    cudaGetSymbolAddress((void**)&Wc,     g_Wc);
    cudaGetSymbolAddress((void**)&bc,     g_bc);
    cudaGetSymbolAddress((void**)&WTpe,   g_WTpe);
    cudaGetSymbolAddress((void**)&WTsage, g_WTsage);

    cudaStream_t s2;
    cudaStreamCreateWithFlags(&s2, cudaStreamNonBlocking);
    cudaEvent_t e0, e_wt, e_csr;
    cudaEventCreateWithFlags(&e0,    cudaEventDisableTiming);
    cudaEventCreateWithFlags(&e_wt,  cudaEventDisableTiming);
    cudaEventCreateWithFlags(&e_csr, cudaEventDisableTiming);

    cudaEventRecord(e0, 0);
    cudaStreamWaitEvent(s2, e0, 0);

    // ---- s2: weight folds + transposes, then CSR/degree chain ----
    for (int l = 0; l < 2; l++) {
        const float* peWpe = peW + (size_t)l * 192 * 128 + 128 * 128;
        fold_w<<<32, 256, 0, s2>>>(pW2 + l * 4096, peWpe, Wc + (size_t)l * 64 * 128);
        fold_b<<<1, 128, 0, s2>>>(pb2 + l * 64, peWpe, peb + l * 128, bc + l * 128);
        transpose_pack<<<(128 * 192 + 255) / 256, 256, 0, s2>>>(
            peW + (size_t)l * 192 * 128, Wc + (size_t)l * 64 * 128,
            WTpe + (size_t)l * 128 * 192, 128, 64);
        for (int e = 0; e < 2; e++) {
            int li = l * 2 + e;
            transpose_pack<<<(128 * 256 + 255) / 256, 256, 0, s2>>>(
                sWl + (size_t)li * 16384, sWr + (size_t)li * 16384,
                WTsage + (size_t)li * 128 * 256, 128, 128);
        }
    }
    cudaEventRecord(e_wt, s2);

    cudaMemsetAsync(cntA, 0, N_A * sizeof(int), s2);
    cudaMemsetAsync(cntB, 0, N_B * sizeof(int), s2);
    count_kernel<<<(NE + 255) / 256, 256, 0, s2>>>(edgeAB + NE, cntB, NE);
    count_kernel<<<(NE + 255) / 256, 256, 0, s2>>>(edgeBA + NE, cntA, NE);
    inv_kernel<<<(N_A + 255) / 256, 256, 0, s2>>>(cntA, invA, N_A);
    inv_kernel<<<(N_B + 255) / 256, 256, 0, s2>>>(cntB, invB, N_B);
    scan_kernel<<<1, 1024, 0, s2>>>(cntA, offA, N_A);
    scan_kernel<<<1, 1024, 0, s2>>>(cntB, offB, N_B);
    cudaMemcpyAsync(cntA, offA, N_A * sizeof(int), cudaMemcpyDeviceToDevice, s2);
    cudaMemcpyAsync(cntB, offB, N_B * sizeof(int), cudaMemcpyDeviceToDevice, s2);
    fill_csr<<<(NE + 255) / 256, 256, 0, s2>>>(edgeAB, edgeAB + NE, cntB, csrAB, NE);
    fill_csr<<<(NE + 255) / 256, 256, 0, s2>>>(edgeBA, edgeBA + NE, cntA, csrBA, NE);
    cudaEventRecord(e_csr, s2);

    // ---- default stream: critical path ----
    cudaMemcpyAsync(agg, PE, (size_t)NT * 8 * sizeof(float), cudaMemcpyDeviceToDevice);
    agg_scatter<<<(EHN + 255) / 256, 256>>>(PE, hedge, hedge + EHN, agg, EHN);
    hid_kernel2<<<(NT + 3) / 4, 256>>>(agg, pW1, pb1, hid, NT);

    cudaStreamWaitEvent(0, e_wt, 0);

    const float* srcA = xA;
    const float* srcB = xB;
    const int blocksA = (N_A + 127) / 128;
    dim3 gGrid(2 * blocksA);
    size_t gsm = GEMM_SMEM_F * sizeof(float);
    float* linB = lin + (size_t)N_A * CC;
    float* mB   = m   + (size_t)N_A * CC;
    bool joined_csr = false;

    for (int l = 0; l < 2; l++) {
        const float* hl = hid + (size_t)l * NT * 64;

        // pe-linear (phi layer-2 folded): lin = [x | relu(h)] @ WTpe^T + bc  (+ bf16 shadow)
        gemm_mma<false><<<gGrid, 256, gsm>>>(
            srcA, srcB, 128,
            hl, hl + (size_t)N_A * 64, 64,
            WTpe + (size_t)l * 128 * 192, WTpe + (size_t)l * 128 * 192, 192,
            bc + l * 128, bc + l * 128,
            nullptr, nullptr, nullptr, nullptr,
            lin, linB, lin16, N_A, N_B, blocksA);

        if (!joined_csr) { cudaStreamWaitEvent(0, e_csr, 0); joined_csr = true; }

        // merged CSR mean gather reading bf16 shadow
        mean_gather2<<<(NT * 32 + 255) / 256, 256>>>(lin16, csrBA, offA, invA,
                                                     csrAB, offB, invB, m);

        float* outA = (l == 1) ? out                    : cur;
        float* outB = (l == 1) ? out + (size_t)N_A * CC : cur + (size_t)N_A * CC;

        gemm_mma<true><<<gGrid, 256, gsm>>>(
            m, mB, 128,
            lin, linB, 128,
            WTsage + (size_t)(l * 2 + 1) * 128 * 256,
            WTsage + (size_t)(l * 2 + 0) * 128 * 256, 256,
            sbl + (l * 2 + 1) * 128, sbl + (l * 2 + 0) * 128,
            lng + (l * 2 + 0) * 128, lnb + (l * 2 + 0) * 128,
            lng + (l * 2 + 1) * 128, lnb + (l * 2 + 1) * 128,
            outA, outB, nullptr, N_A, N_B, blocksA);

        srcA = cur;
        srcB = cur + (size_t)N_A * CC;
    }
}

// round 8
// speedup vs baseline: 2.5751x; 1.0705x over previous
#include <cuda_runtime.h>
#include <cuda_bf16.h>
#include <math.h>
#include <stdint.h>

#define N_A 50000
#define N_B 50000
#define NT  100000
#define NE  800000
#define EHN 1600000
#define CC  128

// ---------------- device scratch (static, no allocation) ----------------
__device__ float g_agg [NT * 8];
__device__ float g_hid [2 * NT * 64];
__device__ float g_lin [NT * CC];          // fp32 (GEMM self-term input)
__device__ __nv_bfloat16 g_lin16[NT * CC]; // bf16 shadow (gather input)
__device__ float g_m   [NT * CC];
__device__ float g_cur [NT * CC];
__device__ int   g_cnt [NT];               // [cntA | cntB]; reused as fill positions
__device__ int   g_offA[N_A + 1];
__device__ int   g_offB[N_B + 1];
__device__ int   g_csrAB[NE];              // src(A) ids grouped by dst(B)
__device__ int   g_csrBA[NE];              // src(B) ids grouped by dst(A)
__device__ float g_Wc   [2 * 64 * 128];
__device__ float g_bc   [2 * 128];
__device__ float g_WTpe  [2 * 128 * 192];
__device__ float g_WTsage[4 * 128 * 256];

// ---------------- helpers ----------------
__device__ __forceinline__ uint32_t smem_u32(const void* p) {
    uint32_t a;
    asm("{ .reg .u64 t; cvta.to.shared.u64 t, %1; cvt.u32.u64 %0, t; }" : "=r"(a) : "l"(p));
    return a;
}

__device__ __forceinline__ uint32_t cvt_tf32(float f) {
    uint32_t r;
    asm("cvt.rna.tf32.f32 %0, %1;" : "=r"(r) : "f"(f));
    return r;
}

__device__ __forceinline__ void mma_tf32(float c[4], const uint32_t a[4],
                                         uint32_t b0, uint32_t b1) {
    asm volatile(
        "mma.sync.aligned.m16n8k8.row.col.f32.tf32.tf32.f32 "
        "{%0,%1,%2,%3}, {%4,%5,%6,%7}, {%8,%9}, {%0,%1,%2,%3};"
        : "+f"(c[0]), "+f"(c[1]), "+f"(c[2]), "+f"(c[3])
        : "r"(a[0]), "r"(a[1]), "r"(a[2]), "r"(a[3]), "r"(b0), "r"(b1));
}

__device__ __forceinline__ void cpasync16(uint32_t daddr, const float* g, bool pred) {
    int sz = pred ? 16 : 0;
    asm volatile("cp.async.cg.shared.global [%0], [%1], 16, %2;"
                 :: "r"(daddr), "l"(g), "r"(sz) : "memory");
}
#define CP_COMMIT() asm volatile("cp.async.commit_group;" ::: "memory")

__device__ __forceinline__ void red4(float* addr, float4 v) {
    asm volatile("red.global.add.v4.f32 [%0], {%1,%2,%3,%4};"
                 :: "l"(addr), "f"(v.x), "f"(v.y), "f"(v.z), "f"(v.w) : "memory");
}

// ---------------- graph preprocessing (merged two-direction kernels) ----------------
// counts for both directions in one launch: [0,NE) -> cntB via dstAB, [NE,2NE) -> cntA via dstBA
__global__ void count2(const int* __restrict__ dstAB, const int* __restrict__ dstBA,
                       int* __restrict__ cntB, int* __restrict__ cntA) {
    int e = blockIdx.x * blockDim.x + threadIdx.x;
    if (e < NE)            atomicAdd(&cntB[dstAB[e]], 1);
    else if (e < 2 * NE)   atomicAdd(&cntA[dstBA[e - NE]], 1);
}

// two independent single-block scans (block 0: A, block 1: B); writes off AND pos (=cnt reuse)
__global__ void scan2(int* __restrict__ cntA, int* __restrict__ offA,
                      int* __restrict__ cntB, int* __restrict__ offB) {
    __shared__ int part[1024];
    int* cnt = blockIdx.x ? cntB : cntA;
    int* off = blockIdx.x ? offB : offA;
    const int N = N_A;                      // N_A == N_B
    int tid = threadIdx.x;
    int chunk = (N + 1023) >> 10;
    int start = tid * chunk;
    int end = min(start + chunk, N);
    int s = 0;
    for (int i = start; i < end; i++) s += cnt[i];
    part[tid] = s;
    __syncthreads();
    for (int o = 1; o < 1024; o <<= 1) {
        int t = (tid >= o) ? part[tid - o] : 0;
        __syncthreads();
        part[tid] += t;
        __syncthreads();
    }
    int pre = part[tid] - s;
    for (int i = start; i < end; i++) {
        int c = cnt[i];
        off[i] = pre;
        cnt[i] = pre;                       // becomes running fill position
        pre += c;
    }
    if (tid == 1023) off[N] = part[1023];
}

// fill both CSRs in one launch
__global__ void fill2(const int* __restrict__ srcAB, const int* __restrict__ dstAB,
                      const int* __restrict__ srcBA, const int* __restrict__ dstBA,
                      int* __restrict__ posB, int* __restrict__ posA,
                      int* __restrict__ csrAB, int* __restrict__ csrBA) {
    int e = blockIdx.x * blockDim.x + threadIdx.x;
    if (e < NE) {
        int p = atomicAdd(&posB[dstAB[e]], 1);
        csrAB[p] = srcAB[e];
    } else if (e < 2 * NE) {
        int i = e - NE;
        int p = atomicAdd(&posA[dstBA[i]], 1);
        csrBA[p] = srcBA[i];
    }
}

__global__ void agg_scatter(const float* __restrict__ PE, const int* __restrict__ hsrc,
                            const int* __restrict__ hdst, float* __restrict__ agg, int E) {
    int e = blockIdx.x * blockDim.x + threadIdx.x;
    if (e >= E) return;
    int s = hsrc[e], d = hdst[e];
    float4 v0 = *(const float4*)(PE + (size_t)s * 8);
    float4 v1 = *(const float4*)(PE + (size_t)s * 8 + 4);
    red4(agg + (size_t)d * 8,     v0);
    red4(agg + (size_t)d * 8 + 4, v1);
}

__global__ void fold_w(const float* __restrict__ W2, const float* __restrict__ peWpe,
                       float* __restrict__ Wc) {
    int idx = blockIdx.x * blockDim.x + threadIdx.x;
    if (idx >= 64 * 128) return;
    int i = idx >> 7, j = idx & 127;
    float s = 0.0f;
    #pragma unroll 8
    for (int p = 0; p < 64; p++) s += W2[i * 64 + p] * peWpe[p * 128 + j];
    Wc[idx] = s;
}

__global__ void fold_b(const float* __restrict__ b2, const float* __restrict__ peWpe,
                       const float* __restrict__ peb, float* __restrict__ bc) {
    int j = threadIdx.x;
    float s = peb[j];
    #pragma unroll 8
    for (int p = 0; p < 64; p++) s += b2[p] * peWpe[p * 128 + j];
    bc[j] = s;
}

__global__ void transpose_pack(const float* __restrict__ Wl, const float* __restrict__ Wr,
                               float* __restrict__ WT, int Kl, int Kr) {
    int K = Kl + Kr;
    int idx = blockIdx.x * blockDim.x + threadIdx.x;
    if (idx >= 128 * K) return;
    int n = idx / K, k = idx % K;
    float w = (k < Kl) ? Wl[(size_t)k * 128 + n] : Wr[(size_t)(k - Kl) * 128 + n];
    WT[idx] = __uint_as_float(cvt_tf32(w));
}

// both layers' hid in one pass over agg
__global__ void hid_kernel2(const float* __restrict__ agg,
                            const float* __restrict__ W1, const float* __restrict__ b1,
                            float* __restrict__ hid, int NTn) {
    __shared__ float sW1[2][512];
    __shared__ float sb1[2][64];
    int tid = threadIdx.x;
    for (int i = tid; i < 512; i += 256) { sW1[0][i] = W1[i]; sW1[1][i] = W1[512 + i]; }
    if (tid < 64) { sb1[0][tid] = b1[tid]; sb1[1][tid] = b1[64 + tid]; }
    __syncthreads();
    int r = tid >> 6, j = tid & 63;
    int row = blockIdx.x * 4 + r;
    if (row < NTn) {
        float a[8];
        #pragma unroll
        for (int k = 0; k < 8; k++) a[k] = agg[(size_t)row * 8 + k];
        #pragma unroll
        for (int l = 0; l < 2; l++) {
            float h = sb1[l][j];
            #pragma unroll
            for (int k = 0; k < 8; k++) h += a[k] * sW1[l][k * 64 + j];
            hid[(size_t)l * NT * 64 + (size_t)row * 64 + j] = fmaxf(h, 0.0f);
        }
    }
}

// ---------------- merged CSR mean gather (bf16 source): one warp per dst row ----------------
__global__ void mean_gather2(const __nv_bfloat16* __restrict__ lin16,
                             const int* __restrict__ csrBA, const int* __restrict__ offA,
                             const int* __restrict__ csrAB, const int* __restrict__ offB,
                             float* __restrict__ m)
{
    int w = (blockIdx.x * blockDim.x + threadIdx.x) >> 5;
    if (w >= NT) return;
    int lane = threadIdx.x & 31;
    const int* csr; const int* off; int srcBase, r;
    if (w < N_A) { csr = csrBA; off = offA; srcBase = N_A; r = w; }
    else         { csr = csrAB; off = offB; srcBase = 0;   r = w - N_A; }
    int s0 = off[r], s1 = off[r + 1];
    float4 acc = make_float4(0.f, 0.f, 0.f, 0.f);
    int i = s0;
    for (; i + 4 <= s1; i += 4) {
        int i0 = __ldg(csr + i),     i1 = __ldg(csr + i + 1);
        int i2 = __ldg(csr + i + 2), i3 = __ldg(csr + i + 3);
        #pragma unroll
        for (int u = 0; u < 4; u++) {
            int sidx = (u == 0) ? i0 : (u == 1) ? i1 : (u == 2) ? i2 : i3;
            uint2 pk = *(const uint2*)(lin16 + (size_t)(srcBase + sidx) * CC + lane * 4);
            __nv_bfloat162 h0 = *(__nv_bfloat162*)&pk.x;
            __nv_bfloat162 h1 = *(__nv_bfloat162*)&pk.y;
            float2 f0 = __bfloat1622float2(h0);
            float2 f1 = __bfloat1622float2(h1);
            acc.x += f0.x; acc.y += f0.y; acc.z += f1.x; acc.w += f1.y;
        }
    }
    for (; i < s1; i++) {
        int sidx = __ldg(csr + i);
        uint2 pk = *(const uint2*)(lin16 + (size_t)(srcBase + sidx) * CC + lane * 4);
        __nv_bfloat162 h0 = *(__nv_bfloat162*)&pk.x;
        __nv_bfloat162 h1 = *(__nv_bfloat162*)&pk.y;
        float2 f0 = __bfloat1622float2(h0);
        float2 f1 = __bfloat1622float2(h1);
        acc.x += f0.x; acc.y += f0.y; acc.z += f1.x; acc.w += f1.y;
    }
    float sc = 1.0f / (float)max(s1 - s0, 1);
    acc.x *= sc; acc.y *= sc; acc.z *= sc; acc.w *= sc;
    *(float4*)(m + (size_t)w * CC + lane * 4) = acc;
}

// ---------------- tf32 mma.sync GEMM (merged A/B launch) ----------------
#define GEMM_SMEM_F (640 + 2 * 2560 + 2 * 2560)
#define TILE_F 2560

__device__ __forceinline__ void load_tile(
    const float* __restrict__ X0, int K0, const float* __restrict__ X1, int K1,
    const float* __restrict__ WT, int K, int m0, int M, int t,
    uint32_t asAddr, uint32_t bsAddr, int tid)
{
    int kb = t * 16;
    #pragma unroll
    for (int i = 0; i < 2; i++) {
        int f = i * 256 + tid;
        int row = f >> 2, q = f & 3;
        int kk = kb + q * 4;
        bool pred = (m0 + row) < M;
        const float* src = (kk < K0)
            ? X0 + (size_t)(m0 + row) * K0 + kk
            : X1 + (size_t)(m0 + row) * K1 + (kk - K0);
        cpasync16(asAddr + (uint32_t)(row * 20 + q * 4) * 4, src, pred);
    }
    #pragma unroll
    for (int i = 0; i < 2; i++) {
        int f = i * 256 + tid;
        int n = f >> 2, q = f & 3;
        cpasync16(bsAddr + (uint32_t)(n * 20 + q * 4) * 4,
                  WT + (size_t)n * K + kb + q * 4, true);
    }
    CP_COMMIT();
}

template<bool DO_LN>
__global__ void __launch_bounds__(256, 2)
gemm_mma(const float* X0a, const float* X0b, int K0,
         const float* X1a, const float* X1b, int K1,
         const float* WTa, const float* WTb, int K,
         const float* biasA, const float* biasB,
         const float* gamA, const float* betA,
         const float* gamB, const float* betB,
         float* outA, float* outB, __nv_bfloat16* out16,
         int Ma, int Mb, int blocksA)
{
    extern __shared__ float sm[];
    float* s_bias  = sm;
    float* s_gamma = sm + 128;
    float* s_beta  = sm + 256;
    float* s_sum   = sm + 384;
    float* s_ss    = sm + 512;
    float* As      = sm + 640;
    float* Bs      = As + 2 * TILE_F;

    bool isB = (int)blockIdx.x >= blocksA;
    const float* X0   = isB ? X0b  : X0a;
    const float* X1   = isB ? X1b  : X1a;
    const float* WT   = isB ? WTb  : WTa;
    const float* bias = isB ? biasB : biasA;
    const float* gamma = isB ? gamB : gamA;
    const float* beta  = isB ? betB : betA;
    float* out = isB ? outB : outA;
    int M  = isB ? Mb : Ma;
    int mrow0 = (isB ? ((int)blockIdx.x - blocksA) : (int)blockIdx.x) * 128;
    size_t row16base = isB ? (size_t)N_A : 0;

    int tid  = threadIdx.x;
    int lane = tid & 31;
    int warp = tid >> 5;
    int wm = warp & 3;
    int wn = warp >> 2;

    if (tid < 128) {
        s_bias[tid] = bias[tid];
        if (DO_LN) {
            s_gamma[tid] = gamma[tid];
            s_beta[tid]  = beta[tid];
            s_sum[tid] = 0.0f;
            s_ss[tid]  = 0.0f;
        }
    }

    uint32_t asAddr = smem_u32(As);
    uint32_t bsAddr = smem_u32(Bs);

    float c[2][8][4];
    #pragma unroll
    for (int mt = 0; mt < 2; mt++)
        #pragma unroll
        for (int nt = 0; nt < 8; nt++)
            #pragma unroll
            for (int j = 0; j < 4; j++) c[mt][nt][j] = 0.0f;

    const int T = K / 16;
    load_tile(X0, K0, X1, K1, WT, K, mrow0, M, 0, asAddr, bsAddr, tid);
    load_tile(X0, K0, X1, K1, WT, K, mrow0, M, 1, asAddr + TILE_F * 4, bsAddr + TILE_F * 4, tid);

    for (int t = 0; t < T; t++) {
        if (t + 1 < T) asm volatile("cp.async.wait_group 1;" ::: "memory");
        else           asm volatile("cp.async.wait_group 0;" ::: "memory");
        __syncthreads();

        const float* Ab = As + (t & 1) * TILE_F;
        const float* Bb = Bs + (t & 1) * TILE_F;
        #pragma unroll
        for (int ks = 0; ks < 2; ks++) {
            int k0 = ks * 8 + (lane & 3);
            uint32_t a[2][4];
            #pragma unroll
            for (int mt = 0; mt < 2; mt++) {
                int rb = wm * 32 + mt * 16 + (lane >> 2);
                a[mt][0] = cvt_tf32(Ab[rb * 20 + k0]);
                a[mt][1] = cvt_tf32(Ab[(rb + 8) * 20 + k0]);
                a[mt][2] = cvt_tf32(Ab[rb * 20 + k0 + 4]);
                a[mt][3] = cvt_tf32(Ab[(rb + 8) * 20 + k0 + 4]);
            }
            #pragma unroll
            for (int nt = 0; nt < 8; nt++) {
                int nb = wn * 64 + nt * 8 + (lane >> 2);
                uint32_t b0 = __float_as_uint(Bb[nb * 20 + k0]);
                uint32_t b1 = __float_as_uint(Bb[nb * 20 + k0 + 4]);
                mma_tf32(c[0][nt], a[0], b0, b1);
                mma_tf32(c[1][nt], a[1], b0, b1);
            }
        }
        __syncthreads();
        if (t + 2 < T)
            load_tile(X0, K0, X1, K1, WT, K, mrow0, M, t + 2,
                      asAddr + (uint32_t)(t & 1) * TILE_F * 4,
                      bsAddr + (uint32_t)(t & 1) * TILE_F * 4, tid);
    }

    #pragma unroll
    for (int nt = 0; nt < 8; nt++) {
        int col = wn * 64 + nt * 8 + 2 * (lane & 3);
        float bx = s_bias[col], by = s_bias[col + 1];
        #pragma unroll
        for (int mt = 0; mt < 2; mt++) {
            c[mt][nt][0] += bx; c[mt][nt][1] += by;
            c[mt][nt][2] += bx; c[mt][nt][3] += by;
        }
    }

    if (!DO_LN) {
        #pragma unroll
        for (int mt = 0; mt < 2; mt++)
            #pragma unroll
            for (int h = 0; h < 2; h++) {
                int rloc = wm * 32 + mt * 16 + (lane >> 2) + h * 8;
                int row = mrow0 + rloc;
                if (row < M) {
                    #pragma unroll
                    for (int nt = 0; nt < 8; nt++) {
                        int col = wn * 64 + nt * 8 + 2 * (lane & 3);
                        float2 o = make_float2(c[mt][nt][h * 2], c[mt][nt][h * 2 + 1]);
                        *(float2*)(out + (size_t)row * 128 + col) = o;
                        __nv_bfloat162 o16 = __float22bfloat162_rn(o);
                        *(__nv_bfloat162*)(out16 + (row16base + row) * 128 + col) = o16;
                    }
                }
            }
        return;
    }

    #pragma unroll
    for (int mt = 0; mt < 2; mt++)
        #pragma unroll
        for (int h = 0; h < 2; h++) {
            float s = 0.f, q = 0.f;
            #pragma unroll
            for (int nt = 0; nt < 8; nt++) {
                float v0 = c[mt][nt][h * 2], v1 = c[mt][nt][h * 2 + 1];
                s += v0 + v1;
                q += v0 * v0 + v1 * v1;
            }
            s += __shfl_xor_sync(0xffffffffu, s, 1);
            s += __shfl_xor_sync(0xffffffffu, s, 2);
            q += __shfl_xor_sync(0xffffffffu, q, 1);
            q += __shfl_xor_sync(0xffffffffu, q, 2);
            if ((lane & 3) == 0) {
                int rl = wm * 32 + mt * 16 + (lane >> 2) + h * 8;
                atomicAdd(&s_sum[rl], s);
                atomicAdd(&s_ss[rl], q);
            }
        }
    __syncthreads();
    #pragma unroll
    for (int mt = 0; mt < 2; mt++)
        #pragma unroll
        for (int h = 0; h < 2; h++) {
            int rl = wm * 32 + mt * 16 + (lane >> 2) + h * 8;
            int row = mrow0 + rl;
            float mu   = s_sum[rl] * (1.0f / 128.0f);
            float var  = s_ss[rl] * (1.0f / 128.0f) - mu * mu;
            float rstd = rsqrtf(var + 1e-5f);
            if (row < M) {
                #pragma unroll
                for (int nt = 0; nt < 8; nt++) {
                    int col = wn * 64 + nt * 8 + 2 * (lane & 3);
                    float2 o;
                    o.x = fmaxf((c[mt][nt][h * 2]     - mu) * rstd * s_gamma[col]     + s_beta[col],     0.f);
                    o.y = fmaxf((c[mt][nt][h * 2 + 1] - mu) * rstd * s_gamma[col + 1] + s_beta[col + 1], 0.f);
                    *(float2*)(out + (size_t)row * 128 + col) = o;
                }
            }
        }
}

// ---------------- launch ----------------
extern "C" void kernel_launch(void* const* d_in, const int* in_sizes, int n_in,
                              void* d_out, int out_size)
{
    const float* xA     = (const float*)d_in[0];
    const float* xB     = (const float*)d_in[1];
    const float* PE     = (const float*)d_in[2];
    const int*   edgeAB = (const int*)  d_in[3];
    const int*   edgeBA = (const int*)  d_in[4];
    const int*   hedge  = (const int*)  d_in[5];
    const float* sWl    = (const float*)d_in[6];
    const float* sbl    = (const float*)d_in[7];
    const float* sWr    = (const float*)d_in[8];
    const float* lng    = (const float*)d_in[9];
    const float* lnb    = (const float*)d_in[10];
    const float* pW1    = (const float*)d_in[11];
    const float* pb1    = (const float*)d_in[12];
    const float* pW2    = (const float*)d_in[13];
    const float* pb2    = (const float*)d_in[14];
    const float* peW    = (const float*)d_in[15];
    const float* peb    = (const float*)d_in[16];
    float* out = (float*)d_out;

    float *agg, *hid, *lin, *m, *cur, *Wc, *bc, *WTpe, *WTsage;
    __nv_bfloat16* lin16;
    int *cnt, *offA, *offB, *csrAB, *csrBA;
    cudaGetSymbolAddress((void**)&agg,    g_agg);
    cudaGetSymbolAddress((void**)&hid,    g_hid);
    cudaGetSymbolAddress((void**)&lin,    g_lin);
    cudaGetSymbolAddress((void**)&lin16,  g_lin16);
    cudaGetSymbolAddress((void**)&m,      g_m);
    cudaGetSymbolAddress((void**)&cur,    g_cur);
    cudaGetSymbolAddress((void**)&cnt,    g_cnt);
    cudaGetSymbolAddress((void**)&offA,   g_offA);
    cudaGetSymbolAddress((void**)&offB,   g_offB);
    cudaGetSymbolAddress((void**)&csrAB,  g_csrAB);
    cudaGetSymbolAddress((void**)&csrBA,  g_csrBA);
    cudaGetSymbolAddress((void**)&Wc,     g_Wc);
    cudaGetSymbolAddress((void**)&bc,     g_bc);
    cudaGetSymbolAddress((void**)&WTpe,   g_WTpe);
    cudaGetSymbolAddress((void**)&WTsage, g_WTsage);
    int* cntA = cnt;
    int* cntB = cnt + N_A;

    cudaStream_t s2;
    cudaStreamCreateWithFlags(&s2, cudaStreamNonBlocking);
    cudaEvent_t e0, e_wt, e_csr;
    cudaEventCreateWithFlags(&e0,    cudaEventDisableTiming);
    cudaEventCreateWithFlags(&e_wt,  cudaEventDisableTiming);
    cudaEventCreateWithFlags(&e_csr, cudaEventDisableTiming);

    cudaEventRecord(e0, 0);
    cudaStreamWaitEvent(s2, e0, 0);

    // ---- s2: weight folds + transposes, then compact CSR chain ----
    for (int l = 0; l < 2; l++) {
        const float* peWpe = peW + (size_t)l * 192 * 128 + 128 * 128;
        fold_w<<<32, 256, 0, s2>>>(pW2 + l * 4096, peWpe, Wc + (size_t)l * 64 * 128);
        fold_b<<<1, 128, 0, s2>>>(pb2 + l * 64, peWpe, peb + l * 128, bc + l * 128);
        transpose_pack<<<(128 * 192 + 255) / 256, 256, 0, s2>>>(
            peW + (size_t)l * 192 * 128, Wc + (size_t)l * 64 * 128,
            WTpe + (size_t)l * 128 * 192, 128, 64);
        for (int e = 0; e < 2; e++) {
            int li = l * 2 + e;
            transpose_pack<<<(128 * 256 + 255) / 256, 256, 0, s2>>>(
                sWl + (size_t)li * 16384, sWr + (size_t)li * 16384,
                WTsage + (size_t)li * 128 * 256, 128, 128);
        }
    }
    cudaEventRecord(e_wt, s2);

    cudaMemsetAsync(cnt, 0, NT * sizeof(int), s2);
    count2<<<(2 * NE + 255) / 256, 256, 0, s2>>>(edgeAB + NE, edgeBA + NE, cntB, cntA);
    scan2<<<2, 1024, 0, s2>>>(cntA, offA, cntB, offB);
    fill2<<<(2 * NE + 255) / 256, 256, 0, s2>>>(edgeAB, edgeAB + NE, edgeBA, edgeBA + NE,
                                                cntB, cntA, csrAB, csrBA);
    cudaEventRecord(e_csr, s2);

    // ---- default stream: critical path ----
    cudaMemcpyAsync(agg, PE, (size_t)NT * 8 * sizeof(float), cudaMemcpyDeviceToDevice);
    agg_scatter<<<(EHN + 255) / 256, 256>>>(PE, hedge, hedge + EHN, agg, EHN);
    hid_kernel2<<<(NT + 3) / 4, 256>>>(agg, pW1, pb1, hid, NT);

    cudaStreamWaitEvent(0, e_wt, 0);

    const float* srcA = xA;
    const float* srcB = xB;
    const int blocksA = (N_A + 127) / 128;
    dim3 gGrid(2 * blocksA);
    size_t gsm = GEMM_SMEM_F * sizeof(float);
    float* linB = lin + (size_t)N_A * CC;
    float* mB   = m   + (size_t)N_A * CC;
    bool joined_csr = false;

    for (int l = 0; l < 2; l++) {
        const float* hl = hid + (size_t)l * NT * 64;

        gemm_mma<false><<<gGrid, 256, gsm>>>(
            srcA, srcB, 128,
            hl, hl + (size_t)N_A * 64, 64,
            WTpe + (size_t)l * 128 * 192, WTpe + (size_t)l * 128 * 192, 192,
            bc + l * 128, bc + l * 128,
            nullptr, nullptr, nullptr, nullptr,
            lin, linB, lin16, N_A, N_B, blocksA);

        if (!joined_csr) { cudaStreamWaitEvent(0, e_csr, 0); joined_csr = true; }

        mean_gather2<<<(NT * 32 + 255) / 256, 256>>>(lin16, csrBA, offA,
                                                     csrAB, offB, m);

        float* outA = (l == 1) ? out                    : cur;
        float* outB = (l == 1) ? out + (size_t)N_A * CC : cur + (size_t)N_A * CC;

        gemm_mma<true><<<gGrid, 256, gsm>>>(
            m, mB, 128,
            lin, linB, 128,
            WTsage + (size_t)(l * 2 + 1) * 128 * 256,
            WTsage + (size_t)(l * 2 + 0) * 128 * 256, 256,
            sbl + (l * 2 + 1) * 128, sbl + (l * 2 + 0) * 128,
            lng + (l * 2 + 0) * 128, lnb + (l * 2 + 0) * 128,
            lng + (l * 2 + 1) * 128, lnb + (l * 2 + 1) * 128,
            outA, outB, nullptr, N_A, N_B, blocksA);

        srcA = cur;
        srcB = cur + (size_t)N_A * CC;
    }
}